// round 3
// baseline (speedup 1.0000x reference)
#include <cuda_runtime.h>
#include <cstddef>

// Problem dims (fixed by the dataset)
#define NROWS 8192   // features rows
#define MROWS 8192   // memory rows
#define HDIM  512

// Scratch: __device__ globals (allowed; no allocation in kernel_launch)
__device__ float g_q[(size_t)NROWS * HDIM];          // 16 MB
__device__ float g_k[(size_t)MROWS * HDIM];          // 16 MB
__device__ float g_s[(size_t)NROWS * MROWS];         // 256 MB

// Tiling
#define BM 128
#define BN 128
#define BK 8
#define TM 8
#define TN 8
#define SPAD 132   // padded smem row (128 + 4) -> conflict-free transpose stores

// ---------------------------------------------------------------------------
// NT GEMM: C[M,N] = A[M,K] @ B[N,K]^T (+ bias[N]).  A,B row-major, K-contig.
// 256 threads, 128x128x8 tile, 8x8 microtile.
// ---------------------------------------------------------------------------
template <bool HAS_BIAS>
__global__ __launch_bounds__(256)
void gemm_nt(const float* __restrict__ A, const float* __restrict__ B,
             const float* __restrict__ bias, float* __restrict__ C,
             int M, int N, int K)
{
    __shared__ float As[BK][SPAD];
    __shared__ float Bs[BK][SPAD];

    const int tid = threadIdx.x;
    const int bm = blockIdx.y * BM;
    const int bn = blockIdx.x * BN;

    // global-load mapping: 128 rows x 8 K-cols = 256 float4
    const int lr = tid >> 1;           // 0..127 (tile row)
    const int lc = (tid & 1) * 4;      // 0 or 4 (k offset)

    // compute mapping: 16x16 thread grid, 8x8 per thread
    const int tx = tid & 15;
    const int ty = tid >> 4;
    const int tm0 = ty * TM;
    const int tn0 = tx * TN;

    const float* Ap = A + (size_t)(bm + lr) * K + lc;
    const float* Bp = B + (size_t)(bn + lr) * K + lc;

    float acc[TM][TN];
#pragma unroll
    for (int i = 0; i < TM; ++i)
#pragma unroll
        for (int j = 0; j < TN; ++j) acc[i][j] = 0.f;

    for (int k0 = 0; k0 < K; k0 += BK) {
        float4 a4 = *(const float4*)(Ap + k0);
        float4 b4 = *(const float4*)(Bp + k0);
        As[lc + 0][lr] = a4.x; As[lc + 1][lr] = a4.y;
        As[lc + 2][lr] = a4.z; As[lc + 3][lr] = a4.w;
        Bs[lc + 0][lr] = b4.x; Bs[lc + 1][lr] = b4.y;
        Bs[lc + 2][lr] = b4.z; Bs[lc + 3][lr] = b4.w;
        __syncthreads();

#pragma unroll
        for (int k = 0; k < BK; ++k) {
            float af[TM], bf[TN];
#pragma unroll
            for (int i = 0; i < TM; ++i) af[i] = As[k][tm0 + i];
#pragma unroll
            for (int j = 0; j < TN; ++j) bf[j] = Bs[k][tn0 + j];
#pragma unroll
            for (int i = 0; i < TM; ++i)
#pragma unroll
                for (int j = 0; j < TN; ++j)
                    acc[i][j] = fmaf(af[i], bf[j], acc[i][j]);
        }
        __syncthreads();
    }

#pragma unroll
    for (int i = 0; i < TM; ++i) {
        float* crow = C + (size_t)(bm + tm0 + i) * N + bn + tn0;
#pragma unroll
        for (int j = 0; j < TN; j += 4) {
            float4 o;
            if (HAS_BIAS) {
                o.x = acc[i][j + 0] + bias[bn + tn0 + j + 0];
                o.y = acc[i][j + 1] + bias[bn + tn0 + j + 1];
                o.z = acc[i][j + 2] + bias[bn + tn0 + j + 2];
                o.w = acc[i][j + 3] + bias[bn + tn0 + j + 3];
            } else {
                o.x = acc[i][j + 0]; o.y = acc[i][j + 1];
                o.z = acc[i][j + 2]; o.w = acc[i][j + 3];
            }
            *(float4*)(crow + j) = o;
        }
    }
}

// ---------------------------------------------------------------------------
// Rowwise softmax, in place. One CTA (256 thr) per row of 8192, 32 elems/thr.
// ---------------------------------------------------------------------------
__global__ __launch_bounds__(256)
void softmax_rows(float* __restrict__ S, int cols)
{
    __shared__ float red[8];
    const int tid = threadIdx.x;
    float4* p = (float4*)(S + (size_t)blockIdx.x * cols);

    float4 v[8];
    float m = -1e30f;
#pragma unroll
    for (int i = 0; i < 8; ++i) {
        v[i] = p[tid + i * 256];
        m = fmaxf(m, fmaxf(fmaxf(v[i].x, v[i].y), fmaxf(v[i].z, v[i].w)));
    }
#pragma unroll
    for (int o = 16; o; o >>= 1) m = fmaxf(m, __shfl_xor_sync(0xffffffffu, m, o));
    if ((tid & 31) == 0) red[tid >> 5] = m;
    __syncthreads();
    if (tid < 32) {
        float t = (tid < 8) ? red[tid] : -1e30f;
#pragma unroll
        for (int o = 4; o; o >>= 1) t = fmaxf(t, __shfl_xor_sync(0xffffffffu, t, o));
        if (tid == 0) red[0] = t;
    }
    __syncthreads();
    m = red[0];
    __syncthreads();   // red[] reused below

    float sum = 0.f;
#pragma unroll
    for (int i = 0; i < 8; ++i) {
        v[i].x = __expf(v[i].x - m);
        v[i].y = __expf(v[i].y - m);
        v[i].z = __expf(v[i].z - m);
        v[i].w = __expf(v[i].w - m);
        sum += (v[i].x + v[i].y) + (v[i].z + v[i].w);
    }
#pragma unroll
    for (int o = 16; o; o >>= 1) sum += __shfl_xor_sync(0xffffffffu, sum, o);
    if ((tid & 31) == 0) red[tid >> 5] = sum;
    __syncthreads();
    if (tid < 32) {
        float t = (tid < 8) ? red[tid] : 0.f;
#pragma unroll
        for (int o = 4; o; o >>= 1) t += __shfl_xor_sync(0xffffffffu, t, o);
        if (tid == 0) red[0] = t;
    }
    __syncthreads();
    const float inv = 1.0f / red[0];

#pragma unroll
    for (int i = 0; i < 8; ++i) {
        v[i].x *= inv; v[i].y *= inv; v[i].z *= inv; v[i].w *= inv;
        p[tid + i * 256] = v[i];
    }
}

// ---------------------------------------------------------------------------
// NN GEMM + merge: out[M,N] = 0.5*F[M,N] + 0.5*(A[M,K] @ B[K,N]).
// A = softmaxed scores (K-contig rows), B = memory_features (N-contig rows).
// ---------------------------------------------------------------------------
__global__ __launch_bounds__(256)
void gemm_nn_merge(const float* __restrict__ A, const float* __restrict__ B,
                   const float* __restrict__ F, float* __restrict__ C,
                   int M, int N, int K)
{
    __shared__ float As[BK][SPAD];
    __shared__ float Bs[BK][SPAD];

    const int tid = threadIdx.x;
    const int bm = blockIdx.y * BM;
    const int bn = blockIdx.x * BN;

    // A tile: 128 rows x 8 k  (K-contiguous rows)
    const int lar = tid >> 1;
    const int lac = (tid & 1) * 4;
    // B tile: 8 k-rows x 128 n (N-contiguous rows)
    const int lbr = tid >> 5;          // 0..7
    const int lbc = (tid & 31) * 4;    // 0..124

    const int tx = tid & 15;
    const int ty = tid >> 4;
    const int tm0 = ty * TM;
    const int tn0 = tx * TN;

    const float* Ap = A + (size_t)(bm + lar) * K + lac;
    const float* Bp = B + (size_t)lbr * N + bn + lbc;

    float acc[TM][TN];
#pragma unroll
    for (int i = 0; i < TM; ++i)
#pragma unroll
        for (int j = 0; j < TN; ++j) acc[i][j] = 0.f;

    for (int k0 = 0; k0 < K; k0 += BK) {
        float4 a4 = *(const float4*)(Ap + k0);
        float4 b4 = *(const float4*)(Bp + (size_t)k0 * N);
        As[lac + 0][lar] = a4.x; As[lac + 1][lar] = a4.y;
        As[lac + 2][lar] = a4.z; As[lac + 3][lar] = a4.w;
        *(float4*)&Bs[lbr][lbc] = b4;
        __syncthreads();

#pragma unroll
        for (int k = 0; k < BK; ++k) {
            float af[TM], bf[TN];
#pragma unroll
            for (int i = 0; i < TM; ++i) af[i] = As[k][tm0 + i];
#pragma unroll
            for (int j = 0; j < TN; ++j) bf[j] = Bs[k][tn0 + j];
#pragma unroll
            for (int i = 0; i < TM; ++i)
#pragma unroll
                for (int j = 0; j < TN; ++j)
                    acc[i][j] = fmaf(af[i], bf[j], acc[i][j]);
        }
        __syncthreads();
    }

#pragma unroll
    for (int i = 0; i < TM; ++i) {
        const size_t roff = (size_t)(bm + tm0 + i) * N + bn + tn0;
        const float* frow = F + roff;
        float* crow = C + roff;
#pragma unroll
        for (int j = 0; j < TN; j += 4) {
            float4 f4 = *(const float4*)(frow + j);
            float4 o;
            o.x = 0.5f * f4.x + 0.5f * acc[i][j + 0];
            o.y = 0.5f * f4.y + 0.5f * acc[i][j + 1];
            o.z = 0.5f * f4.z + 0.5f * acc[i][j + 2];
            o.w = 0.5f * f4.w + 0.5f * acc[i][j + 3];
            *(float4*)(crow + j) = o;
        }
    }
}

// ---------------------------------------------------------------------------
// Launch
// ---------------------------------------------------------------------------
extern "C" void kernel_launch(void* const* d_in, const int* in_sizes, int n_in,
                              void* d_out, int out_size)
{
    const float* features = (const float*)d_in[0];   // [N, H]
    const float* memoryf  = (const float*)d_in[1];   // [M, H]
    const float* Wq       = (const float*)d_in[2];   // [H, H]
    const float* bq       = (const float*)d_in[3];   // [H]
    const float* Wk       = (const float*)d_in[4];   // [H, H]
    const float* bk       = (const float*)d_in[5];   // [H]
    float* out            = (float*)d_out;           // [N, H]

    float *q, *k, *s;
    cudaGetSymbolAddress((void**)&q, g_q);
    cudaGetSymbolAddress((void**)&k, g_k);
    cudaGetSymbolAddress((void**)&s, g_s);

    dim3 blk(256);

    // q = features @ Wq^T + bq   -> [N, H]
    gemm_nt<true><<<dim3(HDIM / BN, NROWS / BM), blk>>>(
        features, Wq, bq, q, NROWS, HDIM, HDIM);

    // k = memory @ Wk^T + bk     -> [M, H]
    gemm_nt<true><<<dim3(HDIM / BN, MROWS / BM), blk>>>(
        memoryf, Wk, bk, k, MROWS, HDIM, HDIM);

    // S = q @ k^T  (tau = 1)     -> [N, M]
    gemm_nt<false><<<dim3(MROWS / BN, NROWS / BM), blk>>>(
        q, k, nullptr, s, NROWS, MROWS, HDIM);

    // rowwise softmax in place
    softmax_rows<<<NROWS, 256>>>(s, MROWS);

    // out = 0.5*features + 0.5*(P @ memory)
    gemm_nn_merge<<<dim3(HDIM / BN, NROWS / BM), blk>>>(
        s, memoryf, features, out, NROWS, HDIM, MROWS);
}

// round 5
// speedup vs baseline: 2.4386x; 2.4386x over previous
#include <cuda_runtime.h>
#include <cuda_fp16.h>
#include <cstdint>
#include <cstddef>

#define NR 8192
#define MR 8192
#define HD 512

// ---------------- scratch (device globals: allowed) ----------------
__device__ __align__(128) __half g_fh[(size_t)NR * HD], g_fl[(size_t)NR * HD];
__device__ __align__(128) __half g_mh[(size_t)MR * HD], g_ml[(size_t)MR * HD];
__device__ __align__(128) __half g_wqh[HD * HD], g_wql[HD * HD];
__device__ __align__(128) __half g_wkh[HD * HD], g_wkl[HD * HD];
__device__ __align__(128) __half g_qh[(size_t)NR * HD], g_ql[(size_t)NR * HD];
__device__ __align__(128) __half g_kh[(size_t)MR * HD], g_kl[(size_t)MR * HD];
__device__ __align__(128) __half g_mth[(size_t)HD * MR], g_mtl[(size_t)HD * MR];
__device__ __align__(128) float  g_s[(size_t)NR * MR];
__device__ __align__(128) __half g_ph[(size_t)NR * MR], g_pl[(size_t)NR * MR];

// ---------------- helpers ----------------
__device__ __forceinline__ uint32_t smem_u32(const void* p) {
    uint32_t a;
    asm("{ .reg .u64 t; cvta.to.shared.u64 t, %1; cvt.u32.u64 %0, t; }" : "=r"(a) : "l"(p));
    return a;
}
__device__ __forceinline__ void cp16(uint32_t dst, const void* src) {
    asm volatile("cp.async.cg.shared.global [%0], [%1], 16;" :: "r"(dst), "l"(src));
}
__device__ __forceinline__ void ldsm4(uint32_t* r, uint32_t addr) {
    asm volatile("ldmatrix.sync.aligned.m8n8.x4.shared.b16 {%0,%1,%2,%3}, [%4];"
        : "=r"(r[0]), "=r"(r[1]), "=r"(r[2]), "=r"(r[3]) : "r"(addr));
}
__device__ __forceinline__ void mma16816(float* c, const uint32_t* a, const uint32_t* b) {
    asm volatile("mma.sync.aligned.m16n8k16.row.col.f32.f16.f16.f32 "
        "{%0,%1,%2,%3}, {%4,%5,%6,%7}, {%8,%9}, {%0,%1,%2,%3};"
        : "+f"(c[0]), "+f"(c[1]), "+f"(c[2]), "+f"(c[3])
        : "r"(a[0]), "r"(a[1]), "r"(a[2]), "r"(a[3]), "r"(b[0]), "r"(b[1]));
}
__device__ __forceinline__ void split1(float v, __half& h, __half& l) {
    h = __float2half_rn(v);
    l = __float2half_rn(v - __half2float(h));
}
__device__ __forceinline__ uint32_t pack2(__half a, __half b) {
    __half2 t = __halves2half2(a, b);
    return *(uint32_t*)&t;
}

// pitch: 32 halfs of data padded to 40 halfs (80B) -> conflict-free ldmatrix
#define PITCH_B 80
#define MAT_B   (128 * PITCH_B)   // 10240 B per matrix tile
#define STAGE_B (4 * MAT_B)       // 40960 B per pipeline stage (Ah,Al,Bh,Bl)
#define NSTAGE  3
#define SMEM_TOT (NSTAGE * STAGE_B)

// ---------------- elementwise fp32 -> (hi, lo) fp16 ----------------
__global__ __launch_bounds__(256)
void split_kernel(const float* __restrict__ s, __half* __restrict__ dh,
                  __half* __restrict__ dl, size_t n4)
{
    size_t i = (size_t)blockIdx.x * blockDim.x + threadIdx.x;
    if (i >= n4) return;
    float4 v = ((const float4*)s)[i];
    __half hx, lx, hy, ly, hz, lz, hw, lw;
    split1(v.x, hx, lx); split1(v.y, hy, ly);
    split1(v.z, hz, lz); split1(v.w, hw, lw);
    ((uint2*)dh)[i] = make_uint2(pack2(hx, hy), pack2(hz, hw));
    ((uint2*)dl)[i] = make_uint2(pack2(lx, ly), pack2(lz, lw));
}

// ---------------- mem [MR][HD] fp32 -> memT [HD][MR] split fp16 ----------------
__global__ __launch_bounds__(256)
void transpose_split(const float* __restrict__ src, __half* __restrict__ dh,
                     __half* __restrict__ dl)
{
    __shared__ float t[32][33];
    const int j0 = blockIdx.x * 32;
    const int h0 = blockIdx.y * 32;
    const int tx = threadIdx.x & 31;
    const int ty = threadIdx.x >> 5;
#pragma unroll
    for (int i = 0; i < 4; ++i)
        t[ty + i * 8][tx] = src[(size_t)(j0 + ty + i * 8) * HD + h0 + tx];
    __syncthreads();
#pragma unroll
    for (int i = 0; i < 4; ++i) {
        float v = t[tx][ty + i * 8];
        __half h, l; split1(v, h, l);
        size_t o = (size_t)(h0 + ty + i * 8) * MR + j0 + tx;
        dh[o] = h; dl[o] = l;
    }
}

// ---------------------------------------------------------------------------
// NT GEMM via mma.sync, split-fp16 operands, fp32 accumulate.
//   D[m][n] = sum_k (Ah+Al)[m][k] * (Bh+Bl)[n][k]   (lo*lo dropped)
// CTA 128x128, K-chunk 32, 3-stage cp.async pipeline.
// 8 warps: 4 (m) x 2 (n); warp tile 32x64.
// EPI: 0 = +bias, write split fp16 (outh/outl)
//      1 = write fp32 (outf)
//      2 = write 0.5*F + 0.5*acc fp32 (outf); F passed via biasF
// ---------------------------------------------------------------------------
template <int EPI>
__global__ __launch_bounds__(256, 1)
void mma_gemm(const __half* __restrict__ Ah, const __half* __restrict__ Al,
              const __half* __restrict__ Bh, const __half* __restrict__ Bl,
              const float* __restrict__ biasF,
              float* __restrict__ outf,
              __half* __restrict__ outh, __half* __restrict__ outl,
              int M, int N, int K)
{
    extern __shared__ char smem[];
    const uint32_t sbase = smem_u32(smem);
    const int tid = threadIdx.x;
    const int wid = tid >> 5;
    const int lane = tid & 31;
    const int bm = blockIdx.y * 128;
    const int bn = blockIdx.x * 128;
    const int wm = (wid & 3) * 32;   // warp m offset in tile
    const int wn = (wid >> 2) * 64;  // warp n offset in tile

    const int NC = K >> 5;           // chunks of 32

    // cooperative chunk load: 4 matrices x 128 rows x 2 chunks-of-16B per thread
    auto loadc = [&](int c) {
        const int stage = c % NSTAGE;
        const int k0 = c << 5;
#pragma unroll
        for (int mt = 0; mt < 4; ++mt) {
            const __half* G = (mt == 0) ? Ah : (mt == 1) ? Al : (mt == 2) ? Bh : Bl;
            const int r0 = (mt < 2) ? bm : bn;
            const uint32_t sb = sbase + stage * STAGE_B + mt * MAT_B;
#pragma unroll
            for (int i = 0; i < 2; ++i) {
                int idx = tid + i * 256;
                int r = idx >> 2, ch = idx & 3;
                cp16(sb + r * PITCH_B + ch * 16,
                     G + (size_t)(r0 + r) * K + k0 + ch * 8);
            }
        }
    };

    float acc[2][8][4];
#pragma unroll
    for (int mg = 0; mg < 2; ++mg)
#pragma unroll
        for (int ng = 0; ng < 8; ++ng)
#pragma unroll
            for (int j = 0; j < 4; ++j) acc[mg][ng][j] = 0.f;

    // prologue: chunks 0 and 1 in flight
    loadc(0);
    asm volatile("cp.async.commit_group;" ::: "memory");
    loadc(1);
    asm volatile("cp.async.commit_group;" ::: "memory");

    // ldmatrix address components (constant per thread)
    const uint32_t aRow = (lane & 15);            // m-row within 16
    const uint32_t aChk = (lane >> 4);            // k 16B chunk
    const uint32_t bRow = ((lane >> 4) & 1) * 8 + (lane & 7);  // n-row within 16
    const uint32_t bChk = (lane >> 3) & 1;        // k 16B chunk

    for (int c = 0; c < NC; ++c) {
        asm volatile("cp.async.wait_group 1;" ::: "memory");
        __syncthreads();
        if (c + 2 < NC) loadc(c + 2);
        asm volatile("cp.async.commit_group;" ::: "memory");

        const uint32_t st = sbase + (c % NSTAGE) * STAGE_B;
        const uint32_t sAh = st, sAl = st + MAT_B, sBh = st + 2 * MAT_B, sBl = st + 3 * MAT_B;

#pragma unroll
        for (int ks = 0; ks < 2; ++ks) {
            uint32_t ah[2][4], al[2][4], bh[4][4], bl[4][4];
#pragma unroll
            for (int mg = 0; mg < 2; ++mg) {
                uint32_t off = (wm + mg * 16 + aRow) * PITCH_B + aChk * 16 + ks * 32;
                ldsm4(ah[mg], sAh + off);
                ldsm4(al[mg], sAl + off);
            }
#pragma unroll
            for (int pr = 0; pr < 4; ++pr) {
                uint32_t off = (wn + pr * 16 + bRow) * PITCH_B + bChk * 16 + ks * 32;
                ldsm4(bh[pr], sBh + off);
                ldsm4(bl[pr], sBl + off);
            }
#pragma unroll
            for (int mg = 0; mg < 2; ++mg)
#pragma unroll
                for (int pr = 0; pr < 4; ++pr) {
                    mma16816(acc[mg][2 * pr + 0], ah[mg], bh[pr] + 0);
                    mma16816(acc[mg][2 * pr + 1], ah[mg], bh[pr] + 2);
                    mma16816(acc[mg][2 * pr + 0], al[mg], bh[pr] + 0);
                    mma16816(acc[mg][2 * pr + 1], al[mg], bh[pr] + 2);
                    mma16816(acc[mg][2 * pr + 0], ah[mg], bl[pr] + 0);
                    mma16816(acc[mg][2 * pr + 1], ah[mg], bl[pr] + 2);
                }
        }
        __syncthreads();
    }

    // ---------------- epilogue (register -> global) ----------------
#pragma unroll
    for (int mg = 0; mg < 2; ++mg) {
        const int r0 = bm + wm + mg * 16 + (lane >> 2);
#pragma unroll
        for (int ng = 0; ng < 8; ++ng) {
            const int cc = bn + wn + ng * 8 + (lane & 3) * 2;
            const float* a = acc[mg][ng];
            if (EPI == 0) {
                float b0 = biasF[cc], b1 = biasF[cc + 1];
                float v0 = a[0] + b0, v1 = a[1] + b1;
                float v2 = a[2] + b0, v3 = a[3] + b1;
                __half h0, l0, h1, l1, h2, l2, h3, l3;
                split1(v0, h0, l0); split1(v1, h1, l1);
                split1(v2, h2, l2); split1(v3, h3, l3);
                *(uint32_t*)(outh + (size_t)r0 * N + cc)       = pack2(h0, h1);
                *(uint32_t*)(outl + (size_t)r0 * N + cc)       = pack2(l0, l1);
                *(uint32_t*)(outh + (size_t)(r0 + 8) * N + cc) = pack2(h2, h3);
                *(uint32_t*)(outl + (size_t)(r0 + 8) * N + cc) = pack2(l2, l3);
            } else if (EPI == 1) {
                *(float2*)(outf + (size_t)r0 * N + cc)       = make_float2(a[0], a[1]);
                *(float2*)(outf + (size_t)(r0 + 8) * N + cc) = make_float2(a[2], a[3]);
            } else {
                size_t o0 = (size_t)r0 * N + cc, o1 = (size_t)(r0 + 8) * N + cc;
                float2 f0 = *(const float2*)(biasF + o0);
                float2 f1 = *(const float2*)(biasF + o1);
                *(float2*)(outf + o0) = make_float2(0.5f * f0.x + 0.5f * a[0],
                                                    0.5f * f0.y + 0.5f * a[1]);
                *(float2*)(outf + o1) = make_float2(0.5f * f1.x + 0.5f * a[2],
                                                    0.5f * f1.y + 0.5f * a[3]);
            }
        }
    }
}

// ---------------- rowwise softmax: fp32 in, split fp16 out ----------------
__global__ __launch_bounds__(256)
void softmax_split(const float* __restrict__ S, __half* __restrict__ Ph,
                   __half* __restrict__ Pl, int cols)
{
    __shared__ float red[8];
    const int tid = threadIdx.x;
    const float4* p = (const float4*)(S + (size_t)blockIdx.x * cols);
    uint2* oh = (uint2*)(Ph + (size_t)blockIdx.x * cols);
    uint2* ol = (uint2*)(Pl + (size_t)blockIdx.x * cols);

    float4 v[8];
    float m = -1e30f;
#pragma unroll
    for (int i = 0; i < 8; ++i) {
        v[i] = p[tid + i * 256];
        m = fmaxf(m, fmaxf(fmaxf(v[i].x, v[i].y), fmaxf(v[i].z, v[i].w)));
    }
#pragma unroll
    for (int o = 16; o; o >>= 1) m = fmaxf(m, __shfl_xor_sync(0xffffffffu, m, o));
    if ((tid & 31) == 0) red[tid >> 5] = m;
    __syncthreads();
    if (tid < 32) {
        float t = (tid < 8) ? red[tid] : -1e30f;
#pragma unroll
        for (int o = 4; o; o >>= 1) t = fmaxf(t, __shfl_xor_sync(0xffffffffu, t, o));
        if (tid == 0) red[0] = t;
    }
    __syncthreads();
    m = red[0];
    __syncthreads();

    float sum = 0.f;
#pragma unroll
    for (int i = 0; i < 8; ++i) {
        v[i].x = __expf(v[i].x - m); v[i].y = __expf(v[i].y - m);
        v[i].z = __expf(v[i].z - m); v[i].w = __expf(v[i].w - m);
        sum += (v[i].x + v[i].y) + (v[i].z + v[i].w);
    }
#pragma unroll
    for (int o = 16; o; o >>= 1) sum += __shfl_xor_sync(0xffffffffu, sum, o);
    if ((tid & 31) == 0) red[tid >> 5] = sum;
    __syncthreads();
    if (tid < 32) {
        float t = (tid < 8) ? red[tid] : 0.f;
#pragma unroll
        for (int o = 4; o; o >>= 1) t += __shfl_xor_sync(0xffffffffu, t, o);
        if (tid == 0) red[0] = t;
    }
    __syncthreads();
    const float inv = 1.0f / red[0];

#pragma unroll
    for (int i = 0; i < 8; ++i) {
        float a = v[i].x * inv, b = v[i].y * inv, c = v[i].z * inv, d = v[i].w * inv;
        __half ha, la, hb, lb, hc, lc, hd, ld;
        split1(a, ha, la); split1(b, hb, lb);
        split1(c, hc, lc); split1(d, hd, ld);
        oh[tid + i * 256] = make_uint2(pack2(ha, hb), pack2(hc, hd));
        ol[tid + i * 256] = make_uint2(pack2(la, lb), pack2(lc, ld));
    }
}

// ---------------------------------------------------------------------------
extern "C" void kernel_launch(void* const* d_in, const int* in_sizes, int n_in,
                              void* d_out, int out_size)
{
    const float* features = (const float*)d_in[0];
    const float* memoryf  = (const float*)d_in[1];
    const float* Wq       = (const float*)d_in[2];
    const float* bq       = (const float*)d_in[3];
    const float* Wk       = (const float*)d_in[4];
    const float* bk       = (const float*)d_in[5];
    float* out            = (float*)d_out;

    __half *fh, *fl, *mh, *ml, *wqh, *wql, *wkh, *wkl;
    __half *qh, *ql, *kh, *kl, *mth, *mtl, *ph, *pl;
    float* s;
    cudaGetSymbolAddress((void**)&fh, g_fh);   cudaGetSymbolAddress((void**)&fl, g_fl);
    cudaGetSymbolAddress((void**)&mh, g_mh);   cudaGetSymbolAddress((void**)&ml, g_ml);
    cudaGetSymbolAddress((void**)&wqh, g_wqh); cudaGetSymbolAddress((void**)&wql, g_wql);
    cudaGetSymbolAddress((void**)&wkh, g_wkh); cudaGetSymbolAddress((void**)&wkl, g_wkl);
    cudaGetSymbolAddress((void**)&qh, g_qh);   cudaGetSymbolAddress((void**)&ql, g_ql);
    cudaGetSymbolAddress((void**)&kh, g_kh);   cudaGetSymbolAddress((void**)&kl, g_kl);
    cudaGetSymbolAddress((void**)&mth, g_mth); cudaGetSymbolAddress((void**)&mtl, g_mtl);
    cudaGetSymbolAddress((void**)&ph, g_ph);   cudaGetSymbolAddress((void**)&pl, g_pl);
    cudaGetSymbolAddress((void**)&s, g_s);

    cudaFuncSetAttribute(mma_gemm<0>, cudaFuncAttributeMaxDynamicSharedMemorySize, SMEM_TOT);
    cudaFuncSetAttribute(mma_gemm<1>, cudaFuncAttributeMaxDynamicSharedMemorySize, SMEM_TOT);
    cudaFuncSetAttribute(mma_gemm<2>, cudaFuncAttributeMaxDynamicSharedMemorySize, SMEM_TOT);

    // 1) split inputs to (hi, lo) fp16
    {
        size_t n4 = (size_t)NR * HD / 4;
        split_kernel<<<(unsigned)((n4 + 255) / 256), 256>>>(features, fh, fl, n4);
        split_kernel<<<(unsigned)((n4 + 255) / 256), 256>>>(memoryf, mh, ml, n4);
        size_t w4 = (size_t)HD * HD / 4;
        split_kernel<<<(unsigned)((w4 + 255) / 256), 256>>>(Wq, wqh, wql, w4);
        split_kernel<<<(unsigned)((w4 + 255) / 256), 256>>>(Wk, wkh, wkl, w4);
    }
    // 2) memT (split) for the AV GEMM
    transpose_split<<<dim3(MR / 32, HD / 32), 256>>>(memoryf, mth, mtl);

    // 3) projections: q = f @ Wq^T + bq, k = mem @ Wk^T + bk (split fp16 out)
    mma_gemm<0><<<dim3(HD / 128, NR / 128), 256, SMEM_TOT>>>(
        fh, fl, wqh, wql, bq, nullptr, qh, ql, NR, HD, HD);
    mma_gemm<0><<<dim3(HD / 128, MR / 128), 256, SMEM_TOT>>>(
        mh, ml, wkh, wkl, bk, nullptr, kh, kl, MR, HD, HD);

    // 4) S = q @ k^T (fp32 out)
    mma_gemm<1><<<dim3(MR / 128, NR / 128), 256, SMEM_TOT>>>(
        qh, ql, kh, kl, nullptr, s, nullptr, nullptr, NR, MR, HD);

    // 5) softmax -> split fp16 P
    softmax_split<<<NR, 256>>>(s, ph, pl, MR);

    // 6) out = 0.5*features + 0.5*(P @ memT^T)
    mma_gemm<2><<<dim3(HD / 128, NR / 128), 256, SMEM_TOT>>>(
        ph, pl, mth, mtl, features, out, nullptr, nullptr, NR, HD, MR);
}

// round 6
// speedup vs baseline: 3.2380x; 1.3278x over previous
#include <cuda_runtime.h>
#include <cuda_fp16.h>
#include <cstdint>
#include <cstddef>

#define NR 8192
#define MR 8192
#define HD 512

// ---------------- scratch (device globals: allowed) ----------------
__device__ __align__(128) __half g_fh[(size_t)NR * HD], g_fl[(size_t)NR * HD];
__device__ __align__(128) __half g_mh[(size_t)MR * HD], g_ml[(size_t)MR * HD];
__device__ __align__(128) __half g_wqh[HD * HD], g_wql[HD * HD];
__device__ __align__(128) __half g_wkh[HD * HD], g_wkl[HD * HD];
__device__ __align__(128) __half g_qh[(size_t)NR * HD], g_ql[(size_t)NR * HD];
__device__ __align__(128) __half g_kh[(size_t)MR * HD], g_kl[(size_t)MR * HD];
__device__ __align__(128) __half g_mth[(size_t)HD * MR], g_mtl[(size_t)HD * MR];
__device__ __align__(128) float  g_s[(size_t)NR * MR];
__device__ __align__(128) __half g_ph[(size_t)NR * MR];

// ---------------- helpers ----------------
__device__ __forceinline__ uint32_t smem_u32(const void* p) {
    uint32_t a;
    asm("{ .reg .u64 t; cvta.to.shared.u64 t, %1; cvt.u32.u64 %0, t; }" : "=r"(a) : "l"(p));
    return a;
}
__device__ __forceinline__ void cp16(uint32_t dst, const void* src) {
    asm volatile("cp.async.cg.shared.global [%0], [%1], 16;" :: "r"(dst), "l"(src));
}
__device__ __forceinline__ void ldsm4(uint32_t* r, uint32_t addr) {
    asm volatile("ldmatrix.sync.aligned.m8n8.x4.shared.b16 {%0,%1,%2,%3}, [%4];"
        : "=r"(r[0]), "=r"(r[1]), "=r"(r[2]), "=r"(r[3]) : "r"(addr));
}
__device__ __forceinline__ void mma16816(float* c, const uint32_t* a, const uint32_t* b) {
    asm volatile("mma.sync.aligned.m16n8k16.row.col.f32.f16.f16.f32 "
        "{%0,%1,%2,%3}, {%4,%5,%6,%7}, {%8,%9}, {%0,%1,%2,%3};"
        : "+f"(c[0]), "+f"(c[1]), "+f"(c[2]), "+f"(c[3])
        : "r"(a[0]), "r"(a[1]), "r"(a[2]), "r"(a[3]), "r"(b[0]), "r"(b[1]));
}
__device__ __forceinline__ void split1(float v, __half& h, __half& l) {
    h = __float2half_rn(v);
    l = __float2half_rn(v - __half2float(h));
}
__device__ __forceinline__ uint32_t pack2(__half a, __half b) {
    __half2 t = __halves2half2(a, b);
    return *(uint32_t*)&t;
}

// pitch: 32 halfs of data padded to 40 halfs (80B) -> conflict-free ldmatrix
#define PITCH_B 80
#define MAT_B   (128 * PITCH_B)   // 10240 B per matrix tile

// ---------------- elementwise fp32 -> (hi, lo) fp16 ----------------
__global__ __launch_bounds__(256)
void split_kernel(const float* __restrict__ s, __half* __restrict__ dh,
                  __half* __restrict__ dl, size_t n4)
{
    size_t i = (size_t)blockIdx.x * blockDim.x + threadIdx.x;
    if (i >= n4) return;
    float4 v = ((const float4*)s)[i];
    __half hx, lx, hy, ly, hz, lz, hw, lw;
    split1(v.x, hx, lx); split1(v.y, hy, ly);
    split1(v.z, hz, lz); split1(v.w, hw, lw);
    ((uint2*)dh)[i] = make_uint2(pack2(hx, hy), pack2(hz, hw));
    ((uint2*)dl)[i] = make_uint2(pack2(lx, ly), pack2(lz, lw));
}

// ---------------- mem [MR][HD] fp32 -> memT [HD][MR] split fp16 ----------------
__global__ __launch_bounds__(256)
void transpose_split(const float* __restrict__ src, __half* __restrict__ dh,
                     __half* __restrict__ dl)
{
    __shared__ float t[32][33];
    const int j0 = blockIdx.x * 32;
    const int h0 = blockIdx.y * 32;
    const int tx = threadIdx.x & 31;
    const int ty = threadIdx.x >> 5;
#pragma unroll
    for (int i = 0; i < 4; ++i)
        t[ty + i * 8][tx] = src[(size_t)(j0 + ty + i * 8) * HD + h0 + tx];
    __syncthreads();
#pragma unroll
    for (int i = 0; i < 4; ++i) {
        float v = t[tx][ty + i * 8];
        __half h, l; split1(v, h, l);
        size_t o = (size_t)(h0 + ty + i * 8) * MR + j0 + tx;
        dh[o] = h; dl[o] = l;
    }
}

// ---------------------------------------------------------------------------
// NT GEMM via mma.sync, split-fp16 operands, fp32 accumulate.
// NPASS==3: D = Ah*Bh + Ah*Bl + Al*Bh    (stage: Ah,Bh,Bl,Al)
// NPASS==2: D = Ah*Bh + Ah*Bl            (stage: Ah,Bh,Bl; Al unused)
// CTA 128x128, K-chunk 32, 2-stage cp.async pipeline, 2 CTAs/SM.
// 8 warps: 4 (m) x 2 (n); warp tile 32x64.
// EPI: 0 = +bias, split fp16 out (outh/outl)
//      1 = fp32 out (outf)
//      2 = 0.5*F + 0.5*acc fp32 out (outf); F passed via biasF
// ---------------------------------------------------------------------------
template <int EPI, int NPASS>
__global__ __launch_bounds__(256, 2)
void mma_gemm(const __half* __restrict__ Ah, const __half* __restrict__ Al,
              const __half* __restrict__ Bh, const __half* __restrict__ Bl,
              const float* __restrict__ biasF,
              float* __restrict__ outf,
              __half* __restrict__ outh, __half* __restrict__ outl,
              int M, int N, int K)
{
    constexpr int NMAT = (NPASS == 3) ? 4 : 3;
    constexpr uint32_t STAGE = NMAT * MAT_B;

    extern __shared__ char smem[];
    const uint32_t sbase = smem_u32(smem);
    const int tid = threadIdx.x;
    const int wid = tid >> 5;
    const int lane = tid & 31;
    const int bm = blockIdx.y * 128;
    const int bn = blockIdx.x * 128;
    const int wm = (wid & 3) * 32;
    const int wn = (wid >> 2) * 64;

    const int NC = K >> 5;

    const int ldr = tid >> 2;          // 0..63 x2
    const int ldc = (tid & 3) * 16;

    auto loadc = [&](int c) {
        const uint32_t sb = sbase + (uint32_t)(c & 1) * STAGE;
        const int k0 = c << 5;
        const __half* pa = Ah + (size_t)(bm + ldr) * K + k0;
        const __half* pb = Bh + (size_t)(bn + ldr) * K + k0;
        const __half* pc = Bl + (size_t)(bn + ldr) * K + k0;
#pragma unroll
        for (int i = 0; i < 2; ++i) {
            cp16(sb + (ldr + i * 64) * PITCH_B + ldc,             pa + (size_t)(i * 64) * K + ldc / 2);
            cp16(sb + MAT_B + (ldr + i * 64) * PITCH_B + ldc,     pb + (size_t)(i * 64) * K + ldc / 2);
            cp16(sb + 2 * MAT_B + (ldr + i * 64) * PITCH_B + ldc, pc + (size_t)(i * 64) * K + ldc / 2);
        }
        if (NPASS == 3) {
            const __half* pd = Al + (size_t)(bm + ldr) * K + k0;
#pragma unroll
            for (int i = 0; i < 2; ++i)
                cp16(sb + 3 * MAT_B + (ldr + i * 64) * PITCH_B + ldc, pd + (size_t)(i * 64) * K + ldc / 2);
        }
    };

    float acc[2][8][4];
#pragma unroll
    for (int mg = 0; mg < 2; ++mg)
#pragma unroll
        for (int ng = 0; ng < 8; ++ng)
#pragma unroll
            for (int j = 0; j < 4; ++j) acc[mg][ng][j] = 0.f;

    loadc(0);
    asm volatile("cp.async.commit_group;" ::: "memory");

    const uint32_t aRow = (lane & 15);
    const uint32_t aChk = (lane >> 4);
    const uint32_t bRow = ((lane >> 4) & 1) * 8 + (lane & 7);
    const uint32_t bChk = (lane >> 3) & 1;

    for (int c = 0; c < NC; ++c) {
        if (c + 1 < NC) {
            loadc(c + 1);
            asm volatile("cp.async.commit_group;" ::: "memory");
            asm volatile("cp.async.wait_group 1;" ::: "memory");
        } else {
            asm volatile("cp.async.wait_group 0;" ::: "memory");
        }
        __syncthreads();

        const uint32_t st = sbase + (uint32_t)(c & 1) * STAGE;
        const uint32_t sAh = st, sBh = st + MAT_B, sBl = st + 2 * MAT_B, sAl = st + 3 * MAT_B;

#pragma unroll
        for (int ks = 0; ks < 2; ++ks) {
            uint32_t ah[2][4], al[2][4];
#pragma unroll
            for (int mg = 0; mg < 2; ++mg) {
                uint32_t off = (wm + mg * 16 + aRow) * PITCH_B + aChk * 16 + ks * 32;
                ldsm4(ah[mg], sAh + off);
                if (NPASS == 3) ldsm4(al[mg], sAl + off);
            }
#pragma unroll
            for (int prh = 0; prh < 2; ++prh) {
                uint32_t bh[2][4], bl[2][4];
#pragma unroll
                for (int p = 0; p < 2; ++p) {
                    uint32_t off = (wn + (prh * 2 + p) * 16 + bRow) * PITCH_B + bChk * 16 + ks * 32;
                    ldsm4(bh[p], sBh + off);
                    ldsm4(bl[p], sBl + off);
                }
#pragma unroll
                for (int mg = 0; mg < 2; ++mg)
#pragma unroll
                    for (int p = 0; p < 2; ++p) {
                        const int ng = 2 * (prh * 2 + p);
                        mma16816(acc[mg][ng + 0], ah[mg], bh[p] + 0);
                        mma16816(acc[mg][ng + 1], ah[mg], bh[p] + 2);
                        mma16816(acc[mg][ng + 0], ah[mg], bl[p] + 0);
                        mma16816(acc[mg][ng + 1], ah[mg], bl[p] + 2);
                        if (NPASS == 3) {
                            mma16816(acc[mg][ng + 0], al[mg], bh[p] + 0);
                            mma16816(acc[mg][ng + 1], al[mg], bh[p] + 2);
                        }
                    }
            }
        }
        __syncthreads();
    }

    // ---------------- epilogue ----------------
#pragma unroll
    for (int mg = 0; mg < 2; ++mg) {
        const int r0 = bm + wm + mg * 16 + (lane >> 2);
#pragma unroll
        for (int ng = 0; ng < 8; ++ng) {
            const int cc = bn + wn + ng * 8 + (lane & 3) * 2;
            const float* a = acc[mg][ng];
            if (EPI == 0) {
                float b0 = biasF[cc], b1 = biasF[cc + 1];
                float v0 = a[0] + b0, v1 = a[1] + b1;
                float v2 = a[2] + b0, v3 = a[3] + b1;
                __half h0, l0, h1, l1, h2, l2, h3, l3;
                split1(v0, h0, l0); split1(v1, h1, l1);
                split1(v2, h2, l2); split1(v3, h3, l3);
                *(uint32_t*)(outh + (size_t)r0 * N + cc)       = pack2(h0, h1);
                *(uint32_t*)(outl + (size_t)r0 * N + cc)       = pack2(l0, l1);
                *(uint32_t*)(outh + (size_t)(r0 + 8) * N + cc) = pack2(h2, h3);
                *(uint32_t*)(outl + (size_t)(r0 + 8) * N + cc) = pack2(l2, l3);
            } else if (EPI == 1) {
                *(float2*)(outf + (size_t)r0 * N + cc)       = make_float2(a[0], a[1]);
                *(float2*)(outf + (size_t)(r0 + 8) * N + cc) = make_float2(a[2], a[3]);
            } else {
                size_t o0 = (size_t)r0 * N + cc, o1 = (size_t)(r0 + 8) * N + cc;
                float2 f0 = *(const float2*)(biasF + o0);
                float2 f1 = *(const float2*)(biasF + o1);
                *(float2*)(outf + o0) = make_float2(0.5f * f0.x + 0.5f * a[0],
                                                    0.5f * f0.y + 0.5f * a[1]);
                *(float2*)(outf + o1) = make_float2(0.5f * f1.x + 0.5f * a[2],
                                                    0.5f * f1.y + 0.5f * a[3]);
            }
        }
    }
}

// ---------------- rowwise softmax: fp32 in, fp16 (hi only) out ----------------
__global__ __launch_bounds__(256)
void softmax_h(const float* __restrict__ S, __half* __restrict__ Ph, int cols)
{
    __shared__ float red[8];
    const int tid = threadIdx.x;
    const float4* p = (const float4*)(S + (size_t)blockIdx.x * cols);
    uint2* oh = (uint2*)(Ph + (size_t)blockIdx.x * cols);

    float4 v[8];
    float m = -1e30f;
#pragma unroll
    for (int i = 0; i < 8; ++i) {
        v[i] = p[tid + i * 256];
        m = fmaxf(m, fmaxf(fmaxf(v[i].x, v[i].y), fmaxf(v[i].z, v[i].w)));
    }
#pragma unroll
    for (int o = 16; o; o >>= 1) m = fmaxf(m, __shfl_xor_sync(0xffffffffu, m, o));
    if ((tid & 31) == 0) red[tid >> 5] = m;
    __syncthreads();
    if (tid < 32) {
        float t = (tid < 8) ? red[tid] : -1e30f;
#pragma unroll
        for (int o = 4; o; o >>= 1) t = fmaxf(t, __shfl_xor_sync(0xffffffffu, t, o));
        if (tid == 0) red[0] = t;
    }
    __syncthreads();
    m = red[0];
    __syncthreads();

    float sum = 0.f;
#pragma unroll
    for (int i = 0; i < 8; ++i) {
        v[i].x = __expf(v[i].x - m); v[i].y = __expf(v[i].y - m);
        v[i].z = __expf(v[i].z - m); v[i].w = __expf(v[i].w - m);
        sum += (v[i].x + v[i].y) + (v[i].z + v[i].w);
    }
#pragma unroll
    for (int o = 16; o; o >>= 1) sum += __shfl_xor_sync(0xffffffffu, sum, o);
    if ((tid & 31) == 0) red[tid >> 5] = sum;
    __syncthreads();
    if (tid < 32) {
        float t = (tid < 8) ? red[tid] : 0.f;
#pragma unroll
        for (int o = 4; o; o >>= 1) t += __shfl_xor_sync(0xffffffffu, t, o);
        if (tid == 0) red[0] = t;
    }
    __syncthreads();
    const float inv = 1.0f / red[0];

#pragma unroll
    for (int i = 0; i < 8; ++i) {
        oh[tid + i * 256] = make_uint2(
            pack2(__float2half_rn(v[i].x * inv), __float2half_rn(v[i].y * inv)),
            pack2(__float2half_rn(v[i].z * inv), __float2half_rn(v[i].w * inv)));
    }
}

// ---------------------------------------------------------------------------
extern "C" void kernel_launch(void* const* d_in, const int* in_sizes, int n_in,
                              void* d_out, int out_size)
{
    const float* features = (const float*)d_in[0];
    const float* memoryf  = (const float*)d_in[1];
    const float* Wq       = (const float*)d_in[2];
    const float* bq       = (const float*)d_in[3];
    const float* Wk       = (const float*)d_in[4];
    const float* bk       = (const float*)d_in[5];
    float* out            = (float*)d_out;

    __half *fh, *fl, *mh, *ml, *wqh, *wql, *wkh, *wkl;
    __half *qh, *ql, *kh, *kl, *mth, *mtl, *ph;
    float* s;
    cudaGetSymbolAddress((void**)&fh, g_fh);   cudaGetSymbolAddress((void**)&fl, g_fl);
    cudaGetSymbolAddress((void**)&mh, g_mh);   cudaGetSymbolAddress((void**)&ml, g_ml);
    cudaGetSymbolAddress((void**)&wqh, g_wqh); cudaGetSymbolAddress((void**)&wql, g_wql);
    cudaGetSymbolAddress((void**)&wkh, g_wkh); cudaGetSymbolAddress((void**)&wkl, g_wkl);
    cudaGetSymbolAddress((void**)&qh, g_qh);   cudaGetSymbolAddress((void**)&ql, g_ql);
    cudaGetSymbolAddress((void**)&kh, g_kh);   cudaGetSymbolAddress((void**)&kl, g_kl);
    cudaGetSymbolAddress((void**)&mth, g_mth); cudaGetSymbolAddress((void**)&mtl, g_mtl);
    cudaGetSymbolAddress((void**)&ph, g_ph);
    cudaGetSymbolAddress((void**)&s, g_s);

    const int SM3 = 2 * 4 * MAT_B;   // 81920 B (3-pass: Ah,Bh,Bl,Al x2 stages)
    const int SM2 = 2 * 3 * MAT_B;   // 61440 B (2-pass: Ah,Bh,Bl x2 stages)
    cudaFuncSetAttribute(mma_gemm<0,3>, cudaFuncAttributeMaxDynamicSharedMemorySize, SM3);
    cudaFuncSetAttribute(mma_gemm<1,3>, cudaFuncAttributeMaxDynamicSharedMemorySize, SM3);
    cudaFuncSetAttribute(mma_gemm<2,2>, cudaFuncAttributeMaxDynamicSharedMemorySize, SM2);

    // 1) split inputs to (hi, lo) fp16
    {
        size_t n4 = (size_t)NR * HD / 4;
        split_kernel<<<(unsigned)((n4 + 255) / 256), 256>>>(features, fh, fl, n4);
        split_kernel<<<(unsigned)((n4 + 255) / 256), 256>>>(memoryf, mh, ml, n4);
        size_t w4 = (size_t)HD * HD / 4;
        split_kernel<<<(unsigned)((w4 + 255) / 256), 256>>>(Wq, wqh, wql, w4);
        split_kernel<<<(unsigned)((w4 + 255) / 256), 256>>>(Wk, wkh, wkl, w4);
    }
    // 2) memT (split) for the AV GEMM
    transpose_split<<<dim3(MR / 32, HD / 32), 256>>>(memoryf, mth, mtl);

    // 3) projections (3-pass, split fp16 out)
    mma_gemm<0,3><<<dim3(HD / 128, NR / 128), 256, SM3>>>(
        fh, fl, wqh, wql, bq, nullptr, qh, ql, NR, HD, HD);
    mma_gemm<0,3><<<dim3(HD / 128, MR / 128), 256, SM3>>>(
        mh, ml, wkh, wkl, bk, nullptr, kh, kl, MR, HD, HD);

    // 4) S = q @ k^T (3-pass, fp32 out)
    mma_gemm<1,3><<<dim3(MR / 128, NR / 128), 256, SM3>>>(
        qh, ql, kh, kl, nullptr, s, nullptr, nullptr, NR, MR, HD);

    // 5) softmax -> fp16 P (hi only)
    softmax_h<<<NR, 256>>>(s, ph, MR);

    // 6) out = 0.5*features + 0.5*(P @ memT^T)  (2-pass)
    mma_gemm<2,2><<<dim3(HD / 128, NR / 128), 256, SM2>>>(
        ph, nullptr, mth, mtl, features, out, nullptr, nullptr, NR, HD, MR);
}

// round 7
// speedup vs baseline: 3.8108x; 1.1769x over previous
#include <cuda_runtime.h>
#include <cuda_fp16.h>
#include <cstdint>
#include <cstddef>

#define NR 8192
#define MR 8192
#define HD 512

// ---------------- scratch (device globals: allowed) ----------------
__device__ __align__(128) __half g_fh[(size_t)NR * HD], g_fl[(size_t)NR * HD];
__device__ __align__(128) __half g_mh[(size_t)MR * HD], g_ml[(size_t)MR * HD];
__device__ __align__(128) __half g_t1h[HD * HD], g_t1l[HD * HD];
__device__ __align__(128) float  g_c[HD];
__device__ __align__(128) __half g_qh[(size_t)NR * HD], g_ql[(size_t)NR * HD];
__device__ __align__(128) __half g_mth[(size_t)HD * MR];
__device__ __align__(128) float  g_s[(size_t)NR * MR];
__device__ __align__(128) __half g_ph[(size_t)NR * MR];

// ---------------- helpers ----------------
__device__ __forceinline__ uint32_t smem_u32(const void* p) {
    uint32_t a;
    asm("{ .reg .u64 t; cvta.to.shared.u64 t, %1; cvt.u32.u64 %0, t; }" : "=r"(a) : "l"(p));
    return a;
}
__device__ __forceinline__ void cp16(uint32_t dst, const void* src) {
    asm volatile("cp.async.cg.shared.global [%0], [%1], 16;" :: "r"(dst), "l"(src));
}
__device__ __forceinline__ void ldsm4(uint32_t* r, uint32_t addr) {
    asm volatile("ldmatrix.sync.aligned.m8n8.x4.shared.b16 {%0,%1,%2,%3}, [%4];"
        : "=r"(r[0]), "=r"(r[1]), "=r"(r[2]), "=r"(r[3]) : "r"(addr));
}
__device__ __forceinline__ void mma16816(float* c, const uint32_t* a, const uint32_t* b) {
    asm volatile("mma.sync.aligned.m16n8k16.row.col.f32.f16.f16.f32 "
        "{%0,%1,%2,%3}, {%4,%5,%6,%7}, {%8,%9}, {%0,%1,%2,%3};"
        : "+f"(c[0]), "+f"(c[1]), "+f"(c[2]), "+f"(c[3])
        : "r"(a[0]), "r"(a[1]), "r"(a[2]), "r"(a[3]), "r"(b[0]), "r"(b[1]));
}
__device__ __forceinline__ void split1(float v, __half& h, __half& l) {
    h = __float2half_rn(v);
    l = __float2half_rn(v - __half2float(h));
}
__device__ __forceinline__ uint32_t pack2(__half a, __half b) {
    __half2 t = __halves2half2(a, b);
    return *(uint32_t*)&t;
}

// pitch: 32 halfs of data padded to 40 halfs (80B) -> conflict-free ldmatrix
#define PITCH_B 80
#define MAT_B   (128 * PITCH_B)   // 10240 B per matrix tile

// ---------------- elementwise fp32 -> (hi, lo) fp16 ----------------
__global__ __launch_bounds__(256)
void split_kernel(const float* __restrict__ s, __half* __restrict__ dh,
                  __half* __restrict__ dl, size_t n4)
{
    size_t i = (size_t)blockIdx.x * blockDim.x + threadIdx.x;
    if (i >= n4) return;
    float4 v = ((const float4*)s)[i];
    __half hx, lx, hy, ly, hz, lz, hw, lw;
    split1(v.x, hx, lx); split1(v.y, hy, ly);
    split1(v.z, hz, lz); split1(v.w, hw, lw);
    ((uint2*)dh)[i] = make_uint2(pack2(hx, hy), pack2(hz, hw));
    ((uint2*)dl)[i] = make_uint2(pack2(lx, ly), pack2(lz, lw));
}

// ---------------- T1 = Wk^T @ Wq (fp32), split-fp16 output ----------------
// T1[i][j] = sum_t Wk[t][i] * Wq[t][j]   (= (Wq^T Wk)^T, the B operand for qw)
__global__ __launch_bounds__(256)
void wprod_kernel(const float* __restrict__ Wk, const float* __restrict__ Wq,
                  __half* __restrict__ Th, __half* __restrict__ Tl)
{
    __shared__ float Ks[16][17], Qs[16][17];
    const int i0 = blockIdx.x * 16;
    const int j0 = blockIdx.y * 16;
    const int tx = threadIdx.x & 15;   // j
    const int ty = threadIdx.x >> 4;   // i
    float acc = 0.f;
    for (int t0 = 0; t0 < HD; t0 += 16) {
        Ks[ty][tx] = Wk[(t0 + ty) * HD + i0 + tx];
        Qs[ty][tx] = Wq[(t0 + ty) * HD + j0 + tx];
        __syncthreads();
#pragma unroll
        for (int t = 0; t < 16; ++t)
            acc = fmaf(Ks[t][ty], Qs[t][tx], acc);
        __syncthreads();
    }
    __half h, l; split1(acc, h, l);
    Th[(size_t)(i0 + ty) * HD + j0 + tx] = h;
    Tl[(size_t)(i0 + ty) * HD + j0 + tx] = l;
}

// ---------------- c = bq @ Wk  (c[j] = sum_t bq[t] * Wk[t][j]) ----------------
__global__ __launch_bounds__(512)
void cvec_kernel(const float* __restrict__ bq, const float* __restrict__ Wk,
                 float* __restrict__ c)
{
    const int j = threadIdx.x;
    float a = 0.f;
    for (int t = 0; t < HD; ++t) a = fmaf(bq[t], Wk[t * HD + j], a);
    c[j] = a;
}

// ---------------- mem [MR][HD] fp32 -> memT [HD][MR] fp16 (hi only) ----------------
__global__ __launch_bounds__(256)
void transpose_h(const float* __restrict__ src, __half* __restrict__ dh)
{
    __shared__ float t[32][33];
    const int j0 = blockIdx.x * 32;
    const int h0 = blockIdx.y * 32;
    const int tx = threadIdx.x & 31;
    const int ty = threadIdx.x >> 5;
#pragma unroll
    for (int i = 0; i < 4; ++i)
        t[ty + i * 8][tx] = src[(size_t)(j0 + ty + i * 8) * HD + h0 + tx];
    __syncthreads();
#pragma unroll
    for (int i = 0; i < 4; ++i) {
        size_t o = (size_t)(h0 + ty + i * 8) * MR + j0 + tx;
        dh[o] = __float2half_rn(t[tx][ty + i * 8]);
    }
}

// ---------------------------------------------------------------------------
// NT GEMM via mma.sync, fp32 accumulate.
// NPASS==3: D = Ah*Bh + Ah*Bl + Al*Bh   (stage mats: Ah,Bh,Bl,Al)
// NPASS==1: D = Ah*Bh                   (stage mats: Ah,Bh)
// CTA 128x128, K-chunk 32, NSTG-stage cp.async pipeline, 2 CTAs/SM.
// 8 warps: 4 (m) x 2 (n); warp tile 32x64.
// EPI: 0 = +bias[n], split fp16 out (outh/outl)
//      1 = fp32 out (outf)
//      2 = 0.5*F + 0.5*acc fp32 out (outf); F passed via biasF
// ---------------------------------------------------------------------------
template <int EPI, int NPASS, int NSTG>
__global__ __launch_bounds__(256, 2)
void mma_gemm(const __half* __restrict__ Ah, const __half* __restrict__ Al,
              const __half* __restrict__ Bh, const __half* __restrict__ Bl,
              const float* __restrict__ biasF,
              float* __restrict__ outf,
              __half* __restrict__ outh, __half* __restrict__ outl,
              int M, int N, int K)
{
    constexpr int NMAT = (NPASS == 3) ? 4 : 2;
    constexpr uint32_t STAGE = NMAT * MAT_B;

    extern __shared__ char smem[];
    const uint32_t sbase = smem_u32(smem);
    const int tid = threadIdx.x;
    const int wid = tid >> 5;
    const int lane = tid & 31;
    const int bm = blockIdx.y * 128;
    const int bn = blockIdx.x * 128;
    const int wm = (wid & 3) * 32;
    const int wn = (wid >> 2) * 64;

    const int NC = K >> 5;

    const int ldr = tid >> 2;
    const int ldc = (tid & 3) * 16;

    auto loadc = [&](int c) {
        const uint32_t sb = sbase + (uint32_t)(c % NSTG) * STAGE;
        const int k0 = c << 5;
        const __half* pa = Ah + (size_t)(bm + ldr) * K + k0 + ldc / 2;
        const __half* pb = Bh + (size_t)(bn + ldr) * K + k0 + ldc / 2;
#pragma unroll
        for (int i = 0; i < 2; ++i) {
            cp16(sb + (ldr + i * 64) * PITCH_B + ldc,         pa + (size_t)(i * 64) * K);
            cp16(sb + MAT_B + (ldr + i * 64) * PITCH_B + ldc, pb + (size_t)(i * 64) * K);
        }
        if (NPASS == 3) {
            const __half* pc = Bl + (size_t)(bn + ldr) * K + k0 + ldc / 2;
            const __half* pd = Al + (size_t)(bm + ldr) * K + k0 + ldc / 2;
#pragma unroll
            for (int i = 0; i < 2; ++i) {
                cp16(sb + 2 * MAT_B + (ldr + i * 64) * PITCH_B + ldc, pc + (size_t)(i * 64) * K);
                cp16(sb + 3 * MAT_B + (ldr + i * 64) * PITCH_B + ldc, pd + (size_t)(i * 64) * K);
            }
        }
    };

    float acc[2][8][4];
#pragma unroll
    for (int mg = 0; mg < 2; ++mg)
#pragma unroll
        for (int ng = 0; ng < 8; ++ng)
#pragma unroll
            for (int j = 0; j < 4; ++j) acc[mg][ng][j] = 0.f;

    const uint32_t aRow = (lane & 15);
    const uint32_t aChk = (lane >> 4);
    const uint32_t bRow = ((lane >> 4) & 1) * 8 + (lane & 7);
    const uint32_t bChk = (lane >> 3) & 1;

    auto compute = [&](int c) {
        const uint32_t st = sbase + (uint32_t)(c % NSTG) * STAGE;
        const uint32_t sAh = st, sBh = st + MAT_B, sBl = st + 2 * MAT_B, sAl = st + 3 * MAT_B;
#pragma unroll
        for (int ks = 0; ks < 2; ++ks) {
            uint32_t ah[2][4], al[2][4];
#pragma unroll
            for (int mg = 0; mg < 2; ++mg) {
                uint32_t off = (wm + mg * 16 + aRow) * PITCH_B + aChk * 16 + ks * 32;
                ldsm4(ah[mg], sAh + off);
                if (NPASS == 3) ldsm4(al[mg], sAl + off);
            }
#pragma unroll
            for (int prh = 0; prh < 2; ++prh) {
                uint32_t bh[2][4], bl[2][4];
#pragma unroll
                for (int p = 0; p < 2; ++p) {
                    uint32_t off = (wn + (prh * 2 + p) * 16 + bRow) * PITCH_B + bChk * 16 + ks * 32;
                    ldsm4(bh[p], sBh + off);
                    if (NPASS == 3) ldsm4(bl[p], sBl + off);
                }
#pragma unroll
                for (int mg = 0; mg < 2; ++mg)
#pragma unroll
                    for (int p = 0; p < 2; ++p) {
                        const int ng = 2 * (prh * 2 + p);
                        mma16816(acc[mg][ng + 0], ah[mg], bh[p] + 0);
                        mma16816(acc[mg][ng + 1], ah[mg], bh[p] + 2);
                        if (NPASS == 3) {
                            mma16816(acc[mg][ng + 0], ah[mg], bl[p] + 0);
                            mma16816(acc[mg][ng + 1], ah[mg], bl[p] + 2);
                            mma16816(acc[mg][ng + 0], al[mg], bh[p] + 0);
                            mma16816(acc[mg][ng + 1], al[mg], bh[p] + 2);
                        }
                    }
            }
        }
    };

    if (NSTG == 2) {
        loadc(0);
        asm volatile("cp.async.commit_group;" ::: "memory");
        for (int c = 0; c < NC; ++c) {
            if (c + 1 < NC) {
                loadc(c + 1);
                asm volatile("cp.async.commit_group;" ::: "memory");
                asm volatile("cp.async.wait_group 1;" ::: "memory");
            } else {
                asm volatile("cp.async.wait_group 0;" ::: "memory");
            }
            __syncthreads();
            compute(c);
            __syncthreads();
        }
    } else {
        loadc(0);
        asm volatile("cp.async.commit_group;" ::: "memory");
        if (NC > 1) {
            loadc(1);
            asm volatile("cp.async.commit_group;" ::: "memory");
        }
        for (int c = 0; c < NC; ++c) {
            if (c + 1 < NC) asm volatile("cp.async.wait_group 1;" ::: "memory");
            else            asm volatile("cp.async.wait_group 0;" ::: "memory");
            __syncthreads();
            if (c + 2 < NC) {
                loadc(c + 2);
                asm volatile("cp.async.commit_group;" ::: "memory");
            }
            compute(c);
        }
    }

    // ---------------- epilogue ----------------
#pragma unroll
    for (int mg = 0; mg < 2; ++mg) {
        const int r0 = bm + wm + mg * 16 + (lane >> 2);
#pragma unroll
        for (int ng = 0; ng < 8; ++ng) {
            const int cc = bn + wn + ng * 8 + (lane & 3) * 2;
            const float* a = acc[mg][ng];
            if (EPI == 0) {
                float b0 = biasF[cc], b1 = biasF[cc + 1];
                float v0 = a[0] + b0, v1 = a[1] + b1;
                float v2 = a[2] + b0, v3 = a[3] + b1;
                __half h0, l0, h1, l1, h2, l2, h3, l3;
                split1(v0, h0, l0); split1(v1, h1, l1);
                split1(v2, h2, l2); split1(v3, h3, l3);
                *(uint32_t*)(outh + (size_t)r0 * N + cc)       = pack2(h0, h1);
                *(uint32_t*)(outl + (size_t)r0 * N + cc)       = pack2(l0, l1);
                *(uint32_t*)(outh + (size_t)(r0 + 8) * N + cc) = pack2(h2, h3);
                *(uint32_t*)(outl + (size_t)(r0 + 8) * N + cc) = pack2(l2, l3);
            } else if (EPI == 1) {
                *(float2*)(outf + (size_t)r0 * N + cc)       = make_float2(a[0], a[1]);
                *(float2*)(outf + (size_t)(r0 + 8) * N + cc) = make_float2(a[2], a[3]);
            } else {
                size_t o0 = (size_t)r0 * N + cc, o1 = (size_t)(r0 + 8) * N + cc;
                float2 f0 = *(const float2*)(biasF + o0);
                float2 f1 = *(const float2*)(biasF + o1);
                *(float2*)(outf + o0) = make_float2(0.5f * f0.x + 0.5f * a[0],
                                                    0.5f * f0.y + 0.5f * a[1]);
                *(float2*)(outf + o1) = make_float2(0.5f * f1.x + 0.5f * a[2],
                                                    0.5f * f1.y + 0.5f * a[3]);
            }
        }
    }
}

// ---------------- rowwise softmax: fp32 in, fp16 (hi only) out ----------------
__global__ __launch_bounds__(256)
void softmax_h(const float* __restrict__ S, __half* __restrict__ Ph, int cols)
{
    __shared__ float red[8];
    const int tid = threadIdx.x;
    const float4* p = (const float4*)(S + (size_t)blockIdx.x * cols);
    uint2* oh = (uint2*)(Ph + (size_t)blockIdx.x * cols);

    float4 v[8];
    float m = -1e30f;
#pragma unroll
    for (int i = 0; i < 8; ++i) {
        v[i] = p[tid + i * 256];
        m = fmaxf(m, fmaxf(fmaxf(v[i].x, v[i].y), fmaxf(v[i].z, v[i].w)));
    }
#pragma unroll
    for (int o = 16; o; o >>= 1) m = fmaxf(m, __shfl_xor_sync(0xffffffffu, m, o));
    if ((tid & 31) == 0) red[tid >> 5] = m;
    __syncthreads();
    if (tid < 32) {
        float t = (tid < 8) ? red[tid] : -1e30f;
#pragma unroll
        for (int o = 4; o; o >>= 1) t = fmaxf(t, __shfl_xor_sync(0xffffffffu, t, o));
        if (tid == 0) red[0] = t;
    }
    __syncthreads();
    m = red[0];
    __syncthreads();

    float sum = 0.f;
#pragma unroll
    for (int i = 0; i < 8; ++i) {
        v[i].x = __expf(v[i].x - m); v[i].y = __expf(v[i].y - m);
        v[i].z = __expf(v[i].z - m); v[i].w = __expf(v[i].w - m);
        sum += (v[i].x + v[i].y) + (v[i].z + v[i].w);
    }
#pragma unroll
    for (int o = 16; o; o >>= 1) sum += __shfl_xor_sync(0xffffffffu, sum, o);
    if ((tid & 31) == 0) red[tid >> 5] = sum;
    __syncthreads();
    if (tid < 32) {
        float t = (tid < 8) ? red[tid] : 0.f;
#pragma unroll
        for (int o = 4; o; o >>= 1) t += __shfl_xor_sync(0xffffffffu, t, o);
        if (tid == 0) red[0] = t;
    }
    __syncthreads();
    const float inv = 1.0f / red[0];

#pragma unroll
    for (int i = 0; i < 8; ++i) {
        oh[tid + i * 256] = make_uint2(
            pack2(__float2half_rn(v[i].x * inv), __float2half_rn(v[i].y * inv)),
            pack2(__float2half_rn(v[i].z * inv), __float2half_rn(v[i].w * inv)));
    }
}

// ---------------------------------------------------------------------------
extern "C" void kernel_launch(void* const* d_in, const int* in_sizes, int n_in,
                              void* d_out, int out_size)
{
    const float* features = (const float*)d_in[0];
    const float* memoryf  = (const float*)d_in[1];
    const float* Wq       = (const float*)d_in[2];
    const float* bq       = (const float*)d_in[3];
    const float* Wk       = (const float*)d_in[4];
    // bk cancels in softmax (per-row logit constant) -> unused
    float* out            = (float*)d_out;

    __half *fh, *fl, *mh, *ml, *t1h, *t1l, *qh, *ql, *mth, *ph;
    float *s, *cv;
    cudaGetSymbolAddress((void**)&fh, g_fh);   cudaGetSymbolAddress((void**)&fl, g_fl);
    cudaGetSymbolAddress((void**)&mh, g_mh);   cudaGetSymbolAddress((void**)&ml, g_ml);
    cudaGetSymbolAddress((void**)&t1h, g_t1h); cudaGetSymbolAddress((void**)&t1l, g_t1l);
    cudaGetSymbolAddress((void**)&qh, g_qh);   cudaGetSymbolAddress((void**)&ql, g_ql);
    cudaGetSymbolAddress((void**)&mth, g_mth); cudaGetSymbolAddress((void**)&ph, g_ph);
    cudaGetSymbolAddress((void**)&s, g_s);     cudaGetSymbolAddress((void**)&cv, g_c);

    const int SM3 = 2 * 4 * MAT_B;   // 81920 B : 3-pass, 2 stages
    const int SM1 = 3 * 2 * MAT_B;   // 61440 B : 1-pass, 3 stages
    cudaFuncSetAttribute(mma_gemm<0,3,2>, cudaFuncAttributeMaxDynamicSharedMemorySize, SM3);
    cudaFuncSetAttribute(mma_gemm<1,3,2>, cudaFuncAttributeMaxDynamicSharedMemorySize, SM3);
    cudaFuncSetAttribute(mma_gemm<2,1,3>, cudaFuncAttributeMaxDynamicSharedMemorySize, SM1);

    // 1) split features & memory to (hi, lo) fp16
    {
        size_t n4 = (size_t)NR * HD / 4;
        split_kernel<<<(unsigned)((n4 + 255) / 256), 256>>>(features, fh, fl, n4);
        split_kernel<<<(unsigned)((n4 + 255) / 256), 256>>>(memoryf, mh, ml, n4);
    }
    // 2) T1 = Wk^T @ Wq (split fp16), c = bq @ Wk
    wprod_kernel<<<dim3(HD / 16, HD / 16), 256>>>(Wk, Wq, t1h, t1l);
    cvec_kernel<<<1, HD>>>(bq, Wk, cv);
    // 3) memT (hi only) for the AV GEMM
    transpose_h<<<dim3(MR / 32, HD / 32), 256>>>(memoryf, mth);

    // 4) qw = f @ W1 + c  (3-pass, split fp16 out)  [replaces q AND k projections]
    mma_gemm<0,3,2><<<dim3(HD / 128, NR / 128), 256, SM3>>>(
        fh, fl, t1h, t1l, cv, nullptr, qh, ql, NR, HD, HD);

    // 5) S = qw @ mem^T  (3-pass, fp32 out)
    mma_gemm<1,3,2><<<dim3(MR / 128, NR / 128), 256, SM3>>>(
        qh, ql, mh, ml, nullptr, s, nullptr, nullptr, NR, MR, HD);

    // 6) softmax -> fp16 P (hi only)
    softmax_h<<<NR, 256>>>(s, ph, MR);

    // 7) out = 0.5*features + 0.5*(P @ memT^T)  (1-pass fp16, 3-stage)
    mma_gemm<2,1,3><<<dim3(HD / 128, NR / 128), 256, SM1>>>(
        ph, nullptr, mth, nullptr, features, out, nullptr, nullptr, NR, HD, MR);
}

// round 8
// speedup vs baseline: 3.9198x; 1.0286x over previous
#include <cuda_runtime.h>
#include <cuda_fp16.h>
#include <cstdint>
#include <cstddef>

#define NR 8192
#define MR 8192
#define HD 512

// ---------------- scratch (device globals: allowed) ----------------
__device__ __align__(128) __half g_fh[(size_t)NR * HD], g_fl[(size_t)NR * HD];
__device__ __align__(128) __half g_mh[(size_t)MR * HD], g_ml[(size_t)MR * HD];
__device__ __align__(128) __half g_t1h[HD * HD], g_t1l[HD * HD];
__device__ __align__(128) float  g_c[HD];
__device__ __align__(128) __half g_qh[(size_t)NR * HD], g_ql[(size_t)NR * HD];
__device__ __align__(128) __half g_mth[(size_t)HD * MR];
__device__ __align__(128) float  g_s[(size_t)NR * MR];
__device__ __align__(128) __half g_ph[(size_t)NR * MR];

// ---------------- helpers ----------------
__device__ __forceinline__ uint32_t smem_u32(const void* p) {
    uint32_t a;
    asm("{ .reg .u64 t; cvta.to.shared.u64 t, %1; cvt.u32.u64 %0, t; }" : "=r"(a) : "l"(p));
    return a;
}
__device__ __forceinline__ void cp16(uint32_t dst, const void* src) {
    asm volatile("cp.async.cg.shared.global [%0], [%1], 16;" :: "r"(dst), "l"(src));
}
__device__ __forceinline__ void ldsm4(uint32_t* r, uint32_t addr) {
    asm volatile("ldmatrix.sync.aligned.m8n8.x4.shared.b16 {%0,%1,%2,%3}, [%4];"
        : "=r"(r[0]), "=r"(r[1]), "=r"(r[2]), "=r"(r[3]) : "r"(addr));
}
__device__ __forceinline__ void mma16816(float* c, const uint32_t* a, const uint32_t* b) {
    asm volatile("mma.sync.aligned.m16n8k16.row.col.f32.f16.f16.f32 "
        "{%0,%1,%2,%3}, {%4,%5,%6,%7}, {%8,%9}, {%0,%1,%2,%3};"
        : "+f"(c[0]), "+f"(c[1]), "+f"(c[2]), "+f"(c[3])
        : "r"(a[0]), "r"(a[1]), "r"(a[2]), "r"(a[3]), "r"(b[0]), "r"(b[1]));
}
__device__ __forceinline__ void split1(float v, __half& h, __half& l) {
    h = __float2half_rn(v);
    l = __float2half_rn(v - __half2float(h));
}
__device__ __forceinline__ uint32_t pack2(__half a, __half b) {
    __half2 t = __halves2half2(a, b);
    return *(uint32_t*)&t;
}

// pitch: 32 halfs of data padded to 40 halfs (80B) -> conflict-free ldmatrix
#define PITCH_B 80
#define MAT_B   (128 * PITCH_B)   // 10240 B per matrix tile

// ---------------- elementwise fp32 -> (hi, lo) fp16 ----------------
__global__ __launch_bounds__(256)
void split_kernel(const float* __restrict__ s, __half* __restrict__ dh,
                  __half* __restrict__ dl, size_t n4)
{
    size_t i = (size_t)blockIdx.x * blockDim.x + threadIdx.x;
    if (i >= n4) return;
    float4 v = ((const float4*)s)[i];
    __half hx, lx, hy, ly, hz, lz, hw, lw;
    split1(v.x, hx, lx); split1(v.y, hy, ly);
    split1(v.z, hz, lz); split1(v.w, hw, lw);
    ((uint2*)dh)[i] = make_uint2(pack2(hx, hy), pack2(hz, hw));
    ((uint2*)dl)[i] = make_uint2(pack2(lx, ly), pack2(lz, lw));
}

// ---------------- T1 = Wk^T @ Wq (fp32), split-fp16 output ----------------
__global__ __launch_bounds__(256)
void wprod_kernel(const float* __restrict__ Wk, const float* __restrict__ Wq,
                  __half* __restrict__ Th, __half* __restrict__ Tl)
{
    __shared__ float Ks[16][17], Qs[16][17];
    const int i0 = blockIdx.x * 16;
    const int j0 = blockIdx.y * 16;
    const int tx = threadIdx.x & 15;
    const int ty = threadIdx.x >> 4;
    float acc = 0.f;
    for (int t0 = 0; t0 < HD; t0 += 16) {
        Ks[ty][tx] = Wk[(t0 + ty) * HD + i0 + tx];
        Qs[ty][tx] = Wq[(t0 + ty) * HD + j0 + tx];
        __syncthreads();
#pragma unroll
        for (int t = 0; t < 16; ++t)
            acc = fmaf(Ks[t][ty], Qs[t][tx], acc);
        __syncthreads();
    }
    __half h, l; split1(acc, h, l);
    Th[(size_t)(i0 + ty) * HD + j0 + tx] = h;
    Tl[(size_t)(i0 + ty) * HD + j0 + tx] = l;
}

// ---------------- c = bq @ Wk, parallel (grid 8 x 256) ----------------
__global__ __launch_bounds__(256)
void cvec_kernel(const float* __restrict__ bq, const float* __restrict__ Wk,
                 float* __restrict__ c)
{
    __shared__ float sm[4][64];
    const int tid = threadIdx.x;
    const int j = blockIdx.x * 64 + (tid & 63);
    const int ts = (tid >> 6) * 128;
    float a = 0.f;
#pragma unroll 4
    for (int t = ts; t < ts + 128; ++t) a = fmaf(bq[t], Wk[t * HD + j], a);
    sm[tid >> 6][tid & 63] = a;
    __syncthreads();
    if (tid < 64)
        c[blockIdx.x * 64 + tid] = (sm[0][tid] + sm[1][tid]) + (sm[2][tid] + sm[3][tid]);
}

// ---------------- mem [MR][HD] fp32 -> memT [HD][MR] fp16 (hi only) ----------------
__global__ __launch_bounds__(256)
void transpose_h(const float* __restrict__ src, __half* __restrict__ dh)
{
    __shared__ float t[32][33];
    const int j0 = blockIdx.x * 32;
    const int h0 = blockIdx.y * 32;
    const int tx = threadIdx.x & 31;
    const int ty = threadIdx.x >> 5;
#pragma unroll
    for (int i = 0; i < 4; ++i)
        t[ty + i * 8][tx] = src[(size_t)(j0 + ty + i * 8) * HD + h0 + tx];
    __syncthreads();
#pragma unroll
    for (int i = 0; i < 4; ++i) {
        size_t o = (size_t)(h0 + ty + i * 8) * MR + j0 + tx;
        dh[o] = __float2half_rn(t[tx][ty + i * 8]);
    }
}

// ---------------------------------------------------------------------------
// NT GEMM via mma.sync, fp32 accumulate.
// NPASS==3: D = Ah*Bh + Ah*Bl + Al*Bh   (stage mats: Ah,Bh,Bl,Al)
// NPASS==1: D = Ah*Bh                   (stage mats: Ah,Bh)
// CTA 128x128, K-chunk 32, NSTG-stage cp.async pipeline (single barrier/chunk),
// 2 CTAs/SM. 8 warps: 4 (m) x 2 (n); warp tile 32x64.
// EPI: 0 = +bias[n], split fp16 out; 1 = fp32 out; 2 = 0.5*F + 0.5*acc (F=biasF)
// ---------------------------------------------------------------------------
template <int EPI, int NPASS, int NSTG>
__global__ __launch_bounds__(256, 2)
void mma_gemm(const __half* __restrict__ Ah, const __half* __restrict__ Al,
              const __half* __restrict__ Bh, const __half* __restrict__ Bl,
              const float* __restrict__ biasF,
              float* __restrict__ outf,
              __half* __restrict__ outh, __half* __restrict__ outl,
              int M, int N, int K)
{
    constexpr int NMAT = (NPASS == 3) ? 4 : 2;
    constexpr uint32_t STAGE = NMAT * MAT_B;

    extern __shared__ char smem[];
    const uint32_t sbase = smem_u32(smem);
    const int tid = threadIdx.x;
    const int wid = tid >> 5;
    const int lane = tid & 31;
    const int bm = blockIdx.y * 128;
    const int bn = blockIdx.x * 128;
    const int wm = (wid & 3) * 32;
    const int wn = (wid >> 2) * 64;

    const int NC = K >> 5;

    const int ldr = tid >> 2;
    const int ldc = (tid & 3) * 16;

    auto loadc = [&](int c) {
        const uint32_t sb = sbase + (uint32_t)(c % NSTG) * STAGE;
        const int k0 = c << 5;
        const __half* pa = Ah + (size_t)(bm + ldr) * K + k0 + ldc / 2;
        const __half* pb = Bh + (size_t)(bn + ldr) * K + k0 + ldc / 2;
#pragma unroll
        for (int i = 0; i < 2; ++i) {
            cp16(sb + (ldr + i * 64) * PITCH_B + ldc,         pa + (size_t)(i * 64) * K);
            cp16(sb + MAT_B + (ldr + i * 64) * PITCH_B + ldc, pb + (size_t)(i * 64) * K);
        }
        if (NPASS == 3) {
            const __half* pc = Bl + (size_t)(bn + ldr) * K + k0 + ldc / 2;
            const __half* pd = Al + (size_t)(bm + ldr) * K + k0 + ldc / 2;
#pragma unroll
            for (int i = 0; i < 2; ++i) {
                cp16(sb + 2 * MAT_B + (ldr + i * 64) * PITCH_B + ldc, pc + (size_t)(i * 64) * K);
                cp16(sb + 3 * MAT_B + (ldr + i * 64) * PITCH_B + ldc, pd + (size_t)(i * 64) * K);
            }
        }
    };

    float acc[2][8][4];
#pragma unroll
    for (int mg = 0; mg < 2; ++mg)
#pragma unroll
        for (int ng = 0; ng < 8; ++ng)
#pragma unroll
            for (int j = 0; j < 4; ++j) acc[mg][ng][j] = 0.f;

    const uint32_t aRow = (lane & 15);
    const uint32_t aChk = (lane >> 4);
    const uint32_t bRow = ((lane >> 4) & 1) * 8 + (lane & 7);
    const uint32_t bChk = (lane >> 3) & 1;

    auto compute = [&](int c) {
        const uint32_t st = sbase + (uint32_t)(c % NSTG) * STAGE;
        const uint32_t sAh = st, sBh = st + MAT_B, sBl = st + 2 * MAT_B, sAl = st + 3 * MAT_B;
#pragma unroll
        for (int ks = 0; ks < 2; ++ks) {
            uint32_t ah[2][4], al[2][4];
#pragma unroll
            for (int mg = 0; mg < 2; ++mg) {
                uint32_t off = (wm + mg * 16 + aRow) * PITCH_B + aChk * 16 + ks * 32;
                ldsm4(ah[mg], sAh + off);
                if (NPASS == 3) ldsm4(al[mg], sAl + off);
            }
#pragma unroll
            for (int prh = 0; prh < 2; ++prh) {
                uint32_t bh[2][4], bl[2][4];
#pragma unroll
                for (int p = 0; p < 2; ++p) {
                    uint32_t off = (wn + (prh * 2 + p) * 16 + bRow) * PITCH_B + bChk * 16 + ks * 32;
                    ldsm4(bh[p], sBh + off);
                    if (NPASS == 3) ldsm4(bl[p], sBl + off);
                }
#pragma unroll
                for (int mg = 0; mg < 2; ++mg)
#pragma unroll
                    for (int p = 0; p < 2; ++p) {
                        const int ng = 2 * (prh * 2 + p);
                        mma16816(acc[mg][ng + 0], ah[mg], bh[p] + 0);
                        mma16816(acc[mg][ng + 1], ah[mg], bh[p] + 2);
                        if (NPASS == 3) {
                            mma16816(acc[mg][ng + 0], ah[mg], bl[p] + 0);
                            mma16816(acc[mg][ng + 1], ah[mg], bl[p] + 2);
                            mma16816(acc[mg][ng + 0], al[mg], bh[p] + 0);
                            mma16816(acc[mg][ng + 1], al[mg], bh[p] + 2);
                        }
                    }
            }
        }
    };

    // single-barrier pipeline: wait(g_c) -> sync -> prefetch(c+NSTG-1) -> compute(c)
#pragma unroll 1
    for (int c = 0; c < NSTG - 1 && c < NC; ++c) {
        loadc(c);
        asm volatile("cp.async.commit_group;" ::: "memory");
    }
#pragma unroll 1
    for (int c = 0; c < NC; ++c) {
        if (NSTG == 3 && c + 2 < NC)
            asm volatile("cp.async.wait_group 1;" ::: "memory");
        else
            asm volatile("cp.async.wait_group 0;" ::: "memory");
        __syncthreads();
        if (c + NSTG - 1 < NC) {
            loadc(c + NSTG - 1);
            asm volatile("cp.async.commit_group;" ::: "memory");
        }
        compute(c);
    }

    // ---------------- epilogue ----------------
#pragma unroll
    for (int mg = 0; mg < 2; ++mg) {
        const int r0 = bm + wm + mg * 16 + (lane >> 2);
#pragma unroll
        for (int ng = 0; ng < 8; ++ng) {
            const int cc = bn + wn + ng * 8 + (lane & 3) * 2;
            const float* a = acc[mg][ng];
            if (EPI == 0) {
                float b0 = biasF[cc], b1 = biasF[cc + 1];
                float v0 = a[0] + b0, v1 = a[1] + b1;
                float v2 = a[2] + b0, v3 = a[3] + b1;
                __half h0, l0, h1, l1, h2, l2, h3, l3;
                split1(v0, h0, l0); split1(v1, h1, l1);
                split1(v2, h2, l2); split1(v3, h3, l3);
                *(uint32_t*)(outh + (size_t)r0 * N + cc)       = pack2(h0, h1);
                *(uint32_t*)(outl + (size_t)r0 * N + cc)       = pack2(l0, l1);
                *(uint32_t*)(outh + (size_t)(r0 + 8) * N + cc) = pack2(h2, h3);
                *(uint32_t*)(outl + (size_t)(r0 + 8) * N + cc) = pack2(l2, l3);
            } else if (EPI == 1) {
                *(float2*)(outf + (size_t)r0 * N + cc)       = make_float2(a[0], a[1]);
                *(float2*)(outf + (size_t)(r0 + 8) * N + cc) = make_float2(a[2], a[3]);
            } else {
                size_t o0 = (size_t)r0 * N + cc, o1 = (size_t)(r0 + 8) * N + cc;
                float2 f0 = *(const float2*)(biasF + o0);
                float2 f1 = *(const float2*)(biasF + o1);
                *(float2*)(outf + o0) = make_float2(0.5f * f0.x + 0.5f * a[0],
                                                    0.5f * f0.y + 0.5f * a[1]);
                *(float2*)(outf + o1) = make_float2(0.5f * f1.x + 0.5f * a[2],
                                                    0.5f * f1.y + 0.5f * a[3]);
            }
        }
    }
}

// ---------------- rowwise softmax: fp32 in, fp16 (hi only) out ----------------
__global__ __launch_bounds__(512)
void softmax_h(const float* __restrict__ S, __half* __restrict__ Ph, int cols)
{
    __shared__ float red[16];
    const int tid = threadIdx.x;
    const float4* p = (const float4*)(S + (size_t)blockIdx.x * cols);
    uint2* oh = (uint2*)(Ph + (size_t)blockIdx.x * cols);

    float4 v[4];
    float m = -1e30f;
#pragma unroll
    for (int i = 0; i < 4; ++i) {
        v[i] = p[tid + i * 512];
        m = fmaxf(m, fmaxf(fmaxf(v[i].x, v[i].y), fmaxf(v[i].z, v[i].w)));
    }
#pragma unroll
    for (int o = 16; o; o >>= 1) m = fmaxf(m, __shfl_xor_sync(0xffffffffu, m, o));
    if ((tid & 31) == 0) red[tid >> 5] = m;
    __syncthreads();
    if (tid < 32) {
        float t = (tid < 16) ? red[tid] : -1e30f;
#pragma unroll
        for (int o = 8; o; o >>= 1) t = fmaxf(t, __shfl_xor_sync(0xffffffffu, t, o));
        if (tid == 0) red[0] = t;
    }
    __syncthreads();
    m = red[0];
    __syncthreads();

    float sum = 0.f;
#pragma unroll
    for (int i = 0; i < 4; ++i) {
        v[i].x = __expf(v[i].x - m); v[i].y = __expf(v[i].y - m);
        v[i].z = __expf(v[i].z - m); v[i].w = __expf(v[i].w - m);
        sum += (v[i].x + v[i].y) + (v[i].z + v[i].w);
    }
#pragma unroll
    for (int o = 16; o; o >>= 1) sum += __shfl_xor_sync(0xffffffffu, sum, o);
    if ((tid & 31) == 0) red[tid >> 5] = sum;
    __syncthreads();
    if (tid < 32) {
        float t = (tid < 16) ? red[tid] : 0.f;
#pragma unroll
        for (int o = 8; o; o >>= 1) t += __shfl_xor_sync(0xffffffffu, t, o);
        if (tid == 0) red[0] = t;
    }
    __syncthreads();
    const float inv = 1.0f / red[0];

#pragma unroll
    for (int i = 0; i < 4; ++i) {
        oh[tid + i * 512] = make_uint2(
            pack2(__float2half_rn(v[i].x * inv), __float2half_rn(v[i].y * inv)),
            pack2(__float2half_rn(v[i].z * inv), __float2half_rn(v[i].w * inv)));
    }
}

// ---------------------------------------------------------------------------
extern "C" void kernel_launch(void* const* d_in, const int* in_sizes, int n_in,
                              void* d_out, int out_size)
{
    const float* features = (const float*)d_in[0];
    const float* memoryf  = (const float*)d_in[1];
    const float* Wq       = (const float*)d_in[2];
    const float* bq       = (const float*)d_in[3];
    const float* Wk       = (const float*)d_in[4];
    // bk cancels in softmax (per-row logit constant) -> unused
    float* out            = (float*)d_out;

    __half *fh, *fl, *mh, *ml, *t1h, *t1l, *qh, *ql, *mth, *ph;
    float *s, *cv;
    cudaGetSymbolAddress((void**)&fh, g_fh);   cudaGetSymbolAddress((void**)&fl, g_fl);
    cudaGetSymbolAddress((void**)&mh, g_mh);   cudaGetSymbolAddress((void**)&ml, g_ml);
    cudaGetSymbolAddress((void**)&t1h, g_t1h); cudaGetSymbolAddress((void**)&t1l, g_t1l);
    cudaGetSymbolAddress((void**)&qh, g_qh);   cudaGetSymbolAddress((void**)&ql, g_ql);
    cudaGetSymbolAddress((void**)&mth, g_mth); cudaGetSymbolAddress((void**)&ph, g_ph);
    cudaGetSymbolAddress((void**)&s, g_s);     cudaGetSymbolAddress((void**)&cv, g_c);

    const int SM3 = 2 * 4 * MAT_B;   // 81920 B : 3-pass, 2 stages
    const int SM1 = 3 * 2 * MAT_B;   // 61440 B : 1-pass, 3 stages
    cudaFuncSetAttribute(mma_gemm<0,3,2>, cudaFuncAttributeMaxDynamicSharedMemorySize, SM3);
    cudaFuncSetAttribute(mma_gemm<1,3,2>, cudaFuncAttributeMaxDynamicSharedMemorySize, SM3);
    cudaFuncSetAttribute(mma_gemm<2,1,3>, cudaFuncAttributeMaxDynamicSharedMemorySize, SM1);

    size_t n4 = (size_t)NR * HD / 4;

    // 1) split features; W-product; bias fold
    split_kernel<<<(unsigned)((n4 + 255) / 256), 256>>>(features, fh, fl, n4);
    wprod_kernel<<<dim3(HD / 16, HD / 16), 256>>>(Wk, Wq, t1h, t1l);
    cvec_kernel<<<HD / 64, 256>>>(bq, Wk, cv);

    // 2) qw = f @ W1 + c  (3-pass, split fp16 out)
    mma_gemm<0,3,2><<<dim3(HD / 128, NR / 128), 256, SM3>>>(
        fh, fl, t1h, t1l, cv, nullptr, qh, ql, NR, HD, HD);

    // 3) split memory; memT
    split_kernel<<<(unsigned)((n4 + 255) / 256), 256>>>(memoryf, mh, ml, n4);
    transpose_h<<<dim3(MR / 32, HD / 32), 256>>>(memoryf, mth);

    // 4) S = qw @ mem^T  (3-pass, fp32 out)
    mma_gemm<1,3,2><<<dim3(MR / 128, NR / 128), 256, SM3>>>(
        qh, ql, mh, ml, nullptr, s, nullptr, nullptr, NR, MR, HD);

    // 5) softmax -> fp16 P (hi only)
    softmax_h<<<NR, 512>>>(s, ph, MR);

    // 6) out = 0.5*features + 0.5*(P @ memT^T)  (1-pass fp16, 3-stage)
    mma_gemm<2,1,3><<<dim3(HD / 128, NR / 128), 256, SM1>>>(
        ph, nullptr, mth, nullptr, features, out, nullptr, nullptr, NR, HD, MR);
}

// round 9
// speedup vs baseline: 4.2495x; 1.0841x over previous
#include <cuda_runtime.h>
#include <cuda_fp16.h>
#include <cstdint>
#include <cstddef>

#define NR 8192
#define MR 8192
#define HD 512

// ---------------- scratch (device globals: allowed) ----------------
__device__ __align__(128) __half g_fh[(size_t)NR * HD], g_fl[(size_t)NR * HD];
__device__ __align__(128) __half g_mh[(size_t)MR * HD], g_ml[(size_t)MR * HD];
__device__ __align__(128) __half g_t1h[HD * HD], g_t1l[HD * HD];
__device__ __align__(128) float  g_c[HD];
__device__ __align__(128) __half g_qh[(size_t)NR * HD], g_ql[(size_t)NR * HD];
__device__ __align__(128) __half g_mth[(size_t)HD * MR];
__device__ __align__(128) float  g_s[(size_t)NR * MR];
__device__ __align__(128) __half g_ph[(size_t)NR * MR];

// ---------------- helpers ----------------
__device__ __forceinline__ uint32_t smem_u32(const void* p) {
    uint32_t a;
    asm("{ .reg .u64 t; cvta.to.shared.u64 t, %1; cvt.u32.u64 %0, t; }" : "=r"(a) : "l"(p));
    return a;
}
__device__ __forceinline__ void cp16(uint32_t dst, const void* src) {
    asm volatile("cp.async.cg.shared.global [%0], [%1], 16;" :: "r"(dst), "l"(src));
}
__device__ __forceinline__ void ldsm4(uint32_t* r, uint32_t addr) {
    asm volatile("ldmatrix.sync.aligned.m8n8.x4.shared.b16 {%0,%1,%2,%3}, [%4];"
        : "=r"(r[0]), "=r"(r[1]), "=r"(r[2]), "=r"(r[3]) : "r"(addr));
}
__device__ __forceinline__ void mma16816(float* c, const uint32_t* a, const uint32_t* b) {
    asm volatile("mma.sync.aligned.m16n8k16.row.col.f32.f16.f16.f32 "
        "{%0,%1,%2,%3}, {%4,%5,%6,%7}, {%8,%9}, {%0,%1,%2,%3};"
        : "+f"(c[0]), "+f"(c[1]), "+f"(c[2]), "+f"(c[3])
        : "r"(a[0]), "r"(a[1]), "r"(a[2]), "r"(a[3]), "r"(b[0]), "r"(b[1]));
}
__device__ __forceinline__ void split1(float v, __half& h, __half& l) {
    h = __float2half_rn(v);
    l = __float2half_rn(v - __half2float(h));
}
__device__ __forceinline__ uint32_t pack2(__half a, __half b) {
    __half2 t = __halves2half2(a, b);
    return *(uint32_t*)&t;
}

// pitch: 32 halfs of data padded to 40 halfs (80B) -> conflict-free ldmatrix
#define PITCH_B 80
#define MAT_B   (128 * PITCH_B)   // 10240 B per matrix tile

// ---------------- elementwise fp32 -> (hi, lo) fp16 ----------------
__global__ __launch_bounds__(256)
void split_kernel(const float* __restrict__ s, __half* __restrict__ dh,
                  __half* __restrict__ dl, size_t n4)
{
    size_t i = (size_t)blockIdx.x * blockDim.x + threadIdx.x;
    if (i >= n4) return;
    float4 v = ((const float4*)s)[i];
    __half hx, lx, hy, ly, hz, lz, hw, lw;
    split1(v.x, hx, lx); split1(v.y, hy, ly);
    split1(v.z, hz, lz); split1(v.w, hw, lw);
    ((uint2*)dh)[i] = make_uint2(pack2(hx, hy), pack2(hz, hw));
    ((uint2*)dl)[i] = make_uint2(pack2(lx, ly), pack2(lz, lw));
}

// ---------------- T1 = Wk^T @ Wq (fp32), split-fp16 output ----------------
__global__ __launch_bounds__(256)
void wprod_kernel(const float* __restrict__ Wk, const float* __restrict__ Wq,
                  __half* __restrict__ Th, __half* __restrict__ Tl)
{
    __shared__ float Ks[16][17], Qs[16][17];
    const int i0 = blockIdx.x * 16;
    const int j0 = blockIdx.y * 16;
    const int tx = threadIdx.x & 15;
    const int ty = threadIdx.x >> 4;
    float acc = 0.f;
    for (int t0 = 0; t0 < HD; t0 += 16) {
        Ks[ty][tx] = Wk[(t0 + ty) * HD + i0 + tx];
        Qs[ty][tx] = Wq[(t0 + ty) * HD + j0 + tx];
        __syncthreads();
#pragma unroll
        for (int t = 0; t < 16; ++t)
            acc = fmaf(Ks[t][ty], Qs[t][tx], acc);
        __syncthreads();
    }
    __half h, l; split1(acc, h, l);
    Th[(size_t)(i0 + ty) * HD + j0 + tx] = h;
    Tl[(size_t)(i0 + ty) * HD + j0 + tx] = l;
}

// ---------------- c = bq @ Wk, parallel ----------------
__global__ __launch_bounds__(256)
void cvec_kernel(const float* __restrict__ bq, const float* __restrict__ Wk,
                 float* __restrict__ c)
{
    __shared__ float sm[4][64];
    const int tid = threadIdx.x;
    const int j = blockIdx.x * 64 + (tid & 63);
    const int ts = (tid >> 6) * 128;
    float a = 0.f;
#pragma unroll 4
    for (int t = ts; t < ts + 128; ++t) a = fmaf(bq[t], Wk[t * HD + j], a);
    sm[tid >> 6][tid & 63] = a;
    __syncthreads();
    if (tid < 64)
        c[blockIdx.x * 64 + tid] = (sm[0][tid] + sm[1][tid]) + (sm[2][tid] + sm[3][tid]);
}

// ---------------- mem [MR][HD] fp32 -> memT [HD][MR] fp16 (hi only) ----------------
__global__ __launch_bounds__(256)
void transpose_h(const float* __restrict__ src, __half* __restrict__ dh)
{
    __shared__ float t[32][33];
    const int j0 = blockIdx.x * 32;
    const int h0 = blockIdx.y * 32;
    const int tx = threadIdx.x & 31;
    const int ty = threadIdx.x >> 5;
#pragma unroll
    for (int i = 0; i < 4; ++i)
        t[ty + i * 8][tx] = src[(size_t)(j0 + ty + i * 8) * HD + h0 + tx];
    __syncthreads();
#pragma unroll
    for (int i = 0; i < 4; ++i) {
        size_t o = (size_t)(h0 + ty + i * 8) * MR + j0 + tx;
        dh[o] = __float2half_rn(t[tx][ty + i * 8]);
    }
}

// ---------------------------------------------------------------------------
// NT GEMM via mma.sync, fp32 accumulate. FAT-WARP layout:
// CTA 128x128, 128 threads, 4 warps 2x2, warp tile 64x64 (128 accum regs/thr).
// NPASS==3: D = Ah*Bh + Ah*Bl + Al*Bh   (stage mats: Ah,Bh,Bl,Al)
// NPASS==1: D = Ah*Bh                   (stage mats: Ah,Bh)
// K-chunk 32, NSTG-stage cp.async pipeline, single barrier per chunk, 2 CTAs/SM.
// EPI: 0 = +bias[n], split fp16 out; 1 = fp32 out; 2 = 0.5*F + 0.5*acc (F=biasF)
// ---------------------------------------------------------------------------
template <int EPI, int NPASS, int NSTG>
__global__ __launch_bounds__(128, 2)
void mma_gemm(const __half* __restrict__ Ah, const __half* __restrict__ Al,
              const __half* __restrict__ Bh, const __half* __restrict__ Bl,
              const float* __restrict__ biasF,
              float* __restrict__ outf,
              __half* __restrict__ outh, __half* __restrict__ outl,
              int M, int N, int K)
{
    constexpr int NMAT = (NPASS == 3) ? 4 : 2;
    constexpr uint32_t STAGE = NMAT * MAT_B;

    extern __shared__ char smem[];
    const uint32_t sbase = smem_u32(smem);
    const int tid = threadIdx.x;
    const int wid = tid >> 5;           // 0..3
    const int lane = tid & 31;
    const int bm = blockIdx.y * 128;
    const int bn = blockIdx.x * 128;
    const int wm = (wid & 1) * 64;
    const int wn = (wid >> 1) * 64;

    const int NC = K >> 5;

    const int ldr = tid >> 2;           // 0..31
    const int ldc = (tid & 3) * 16;

    auto loadc = [&](int c) {
        const uint32_t sb = sbase + (uint32_t)(c % NSTG) * STAGE;
        const int k0 = c << 5;
        const __half* pa = Ah + (size_t)(bm + ldr) * K + k0 + ldc / 2;
        const __half* pb = Bh + (size_t)(bn + ldr) * K + k0 + ldc / 2;
#pragma unroll
        for (int i = 0; i < 4; ++i) {
            cp16(sb + (ldr + i * 32) * PITCH_B + ldc,         pa + (size_t)(i * 32) * K);
            cp16(sb + MAT_B + (ldr + i * 32) * PITCH_B + ldc, pb + (size_t)(i * 32) * K);
        }
        if (NPASS == 3) {
            const __half* pc = Bl + (size_t)(bn + ldr) * K + k0 + ldc / 2;
            const __half* pd = Al + (size_t)(bm + ldr) * K + k0 + ldc / 2;
#pragma unroll
            for (int i = 0; i < 4; ++i) {
                cp16(sb + 2 * MAT_B + (ldr + i * 32) * PITCH_B + ldc, pc + (size_t)(i * 32) * K);
                cp16(sb + 3 * MAT_B + (ldr + i * 32) * PITCH_B + ldc, pd + (size_t)(i * 32) * K);
            }
        }
    };

    float acc[4][8][4];
#pragma unroll
    for (int mg = 0; mg < 4; ++mg)
#pragma unroll
        for (int ng = 0; ng < 8; ++ng)
#pragma unroll
            for (int j = 0; j < 4; ++j) acc[mg][ng][j] = 0.f;

    const uint32_t aRow = (lane & 15);
    const uint32_t aChk = (lane >> 4);
    const uint32_t bRow = ((lane >> 4) & 1) * 8 + (lane & 7);
    const uint32_t bChk = (lane >> 3) & 1;

    auto compute = [&](int c) {
        const uint32_t st = sbase + (uint32_t)(c % NSTG) * STAGE;
#pragma unroll
        for (int ks = 0; ks < 2; ++ks) {
            uint32_t ah[4][4], al[4][4];
#pragma unroll
            for (int mg = 0; mg < 4; ++mg) {
                uint32_t off = (wm + mg * 16 + aRow) * PITCH_B + aChk * 16 + ks * 32;
                ldsm4(ah[mg], st + off);
                if (NPASS == 3) ldsm4(al[mg], st + 3 * MAT_B + off);
            }
#pragma unroll
            for (int p = 0; p < 4; ++p) {
                uint32_t bh[4], bl[4];
                uint32_t off = (wn + p * 16 + bRow) * PITCH_B + bChk * 16 + ks * 32;
                ldsm4(bh, st + MAT_B + off);
                if (NPASS == 3) ldsm4(bl, st + 2 * MAT_B + off);
                const int ng = 2 * p;
#pragma unroll
                for (int mg = 0; mg < 4; ++mg) {
                    mma16816(acc[mg][ng + 0], ah[mg], bh + 0);
                    mma16816(acc[mg][ng + 1], ah[mg], bh + 2);
                    if (NPASS == 3) {
                        mma16816(acc[mg][ng + 0], ah[mg], bl + 0);
                        mma16816(acc[mg][ng + 1], ah[mg], bl + 2);
                        mma16816(acc[mg][ng + 0], al[mg], bh + 0);
                        mma16816(acc[mg][ng + 1], al[mg], bh + 2);
                    }
                }
            }
        }
    };

    // pipeline: wait(chunk c) -> sync -> prefetch(c+NSTG-1) -> compute(c)
#pragma unroll 1
    for (int c = 0; c < NSTG - 1 && c < NC; ++c) {
        loadc(c);
        asm volatile("cp.async.commit_group;" ::: "memory");
    }
#pragma unroll 1
    for (int c = 0; c < NC; ++c) {
        if (NSTG >= 4 && c + 2 < NC)
            asm volatile("cp.async.wait_group 2;" ::: "memory");
        else if (NSTG >= 3 && c + 1 < NC)
            asm volatile("cp.async.wait_group 1;" ::: "memory");
        else
            asm volatile("cp.async.wait_group 0;" ::: "memory");
        __syncthreads();
        if (c + NSTG - 1 < NC) {
            loadc(c + NSTG - 1);
            asm volatile("cp.async.commit_group;" ::: "memory");
        }
        compute(c);
    }

    // ---------------- epilogue ----------------
#pragma unroll
    for (int mg = 0; mg < 4; ++mg) {
        const int r0 = bm + wm + mg * 16 + (lane >> 2);
#pragma unroll
        for (int ng = 0; ng < 8; ++ng) {
            const int cc = bn + wn + ng * 8 + (lane & 3) * 2;
            const float* a = acc[mg][ng];
            if (EPI == 0) {
                float b0 = biasF[cc], b1 = biasF[cc + 1];
                float v0 = a[0] + b0, v1 = a[1] + b1;
                float v2 = a[2] + b0, v3 = a[3] + b1;
                __half h0, l0, h1, l1, h2, l2, h3, l3;
                split1(v0, h0, l0); split1(v1, h1, l1);
                split1(v2, h2, l2); split1(v3, h3, l3);
                *(uint32_t*)(outh + (size_t)r0 * N + cc)       = pack2(h0, h1);
                *(uint32_t*)(outl + (size_t)r0 * N + cc)       = pack2(l0, l1);
                *(uint32_t*)(outh + (size_t)(r0 + 8) * N + cc) = pack2(h2, h3);
                *(uint32_t*)(outl + (size_t)(r0 + 8) * N + cc) = pack2(l2, l3);
            } else if (EPI == 1) {
                *(float2*)(outf + (size_t)r0 * N + cc)       = make_float2(a[0], a[1]);
                *(float2*)(outf + (size_t)(r0 + 8) * N + cc) = make_float2(a[2], a[3]);
            } else {
                size_t o0 = (size_t)r0 * N + cc, o1 = (size_t)(r0 + 8) * N + cc;
                float2 f0 = *(const float2*)(biasF + o0);
                float2 f1 = *(const float2*)(biasF + o1);
                *(float2*)(outf + o0) = make_float2(0.5f * f0.x + 0.5f * a[0],
                                                    0.5f * f0.y + 0.5f * a[1]);
                *(float2*)(outf + o1) = make_float2(0.5f * f1.x + 0.5f * a[2],
                                                    0.5f * f1.y + 0.5f * a[3]);
            }
        }
    }
}

// ---------------- rowwise softmax: fp32 in, fp16 (hi only) out ----------------
__global__ __launch_bounds__(512)
void softmax_h(const float* __restrict__ S, __half* __restrict__ Ph, int cols)
{
    __shared__ float red[16];
    const int tid = threadIdx.x;
    const float4* p = (const float4*)(S + (size_t)blockIdx.x * cols);
    uint2* oh = (uint2*)(Ph + (size_t)blockIdx.x * cols);

    float4 v[4];
    float m = -1e30f;
#pragma unroll
    for (int i = 0; i < 4; ++i) {
        v[i] = p[tid + i * 512];
        m = fmaxf(m, fmaxf(fmaxf(v[i].x, v[i].y), fmaxf(v[i].z, v[i].w)));
    }
#pragma unroll
    for (int o = 16; o; o >>= 1) m = fmaxf(m, __shfl_xor_sync(0xffffffffu, m, o));
    if ((tid & 31) == 0) red[tid >> 5] = m;
    __syncthreads();
    if (tid < 32) {
        float t = (tid < 16) ? red[tid] : -1e30f;
#pragma unroll
        for (int o = 8; o; o >>= 1) t = fmaxf(t, __shfl_xor_sync(0xffffffffu, t, o));
        if (tid == 0) red[0] = t;
    }
    __syncthreads();
    m = red[0];
    __syncthreads();

    float sum = 0.f;
#pragma unroll
    for (int i = 0; i < 4; ++i) {
        v[i].x = __expf(v[i].x - m); v[i].y = __expf(v[i].y - m);
        v[i].z = __expf(v[i].z - m); v[i].w = __expf(v[i].w - m);
        sum += (v[i].x + v[i].y) + (v[i].z + v[i].w);
    }
#pragma unroll
    for (int o = 16; o; o >>= 1) sum += __shfl_xor_sync(0xffffffffu, sum, o);
    if ((tid & 31) == 0) red[tid >> 5] = sum;
    __syncthreads();
    if (tid < 32) {
        float t = (tid < 16) ? red[tid] : 0.f;
#pragma unroll
        for (int o = 8; o; o >>= 1) t += __shfl_xor_sync(0xffffffffu, t, o);
        if (tid == 0) red[0] = t;
    }
    __syncthreads();
    const float inv = 1.0f / red[0];

#pragma unroll
    for (int i = 0; i < 4; ++i) {
        oh[tid + i * 512] = make_uint2(
            pack2(__float2half_rn(v[i].x * inv), __float2half_rn(v[i].y * inv)),
            pack2(__float2half_rn(v[i].z * inv), __float2half_rn(v[i].w * inv)));
    }
}

// ---------------------------------------------------------------------------
extern "C" void kernel_launch(void* const* d_in, const int* in_sizes, int n_in,
                              void* d_out, int out_size)
{
    const float* features = (const float*)d_in[0];
    const float* memoryf  = (const float*)d_in[1];
    const float* Wq       = (const float*)d_in[2];
    const float* bq       = (const float*)d_in[3];
    const float* Wk       = (const float*)d_in[4];
    // bk cancels in softmax (per-row logit constant) -> unused
    float* out            = (float*)d_out;

    __half *fh, *fl, *mh, *ml, *t1h, *t1l, *qh, *ql, *mth, *ph;
    float *s, *cv;
    cudaGetSymbolAddress((void**)&fh, g_fh);   cudaGetSymbolAddress((void**)&fl, g_fl);
    cudaGetSymbolAddress((void**)&mh, g_mh);   cudaGetSymbolAddress((void**)&ml, g_ml);
    cudaGetSymbolAddress((void**)&t1h, g_t1h); cudaGetSymbolAddress((void**)&t1l, g_t1l);
    cudaGetSymbolAddress((void**)&qh, g_qh);   cudaGetSymbolAddress((void**)&ql, g_ql);
    cudaGetSymbolAddress((void**)&mth, g_mth); cudaGetSymbolAddress((void**)&ph, g_ph);
    cudaGetSymbolAddress((void**)&s, g_s);     cudaGetSymbolAddress((void**)&cv, g_c);

    const int SM3 = 2 * 4 * MAT_B;   // 81920 B : 3-pass, 2 stages
    const int SM1 = 4 * 2 * MAT_B;   // 81920 B : 1-pass, 4 stages
    cudaFuncSetAttribute(mma_gemm<0,3,2>, cudaFuncAttributeMaxDynamicSharedMemorySize, SM3);
    cudaFuncSetAttribute(mma_gemm<1,3,2>, cudaFuncAttributeMaxDynamicSharedMemorySize, SM3);
    cudaFuncSetAttribute(mma_gemm<2,1,4>, cudaFuncAttributeMaxDynamicSharedMemorySize, SM1);

    size_t n4 = (size_t)NR * HD / 4;

    // 1) split features; W-product; bias fold
    split_kernel<<<(unsigned)((n4 + 255) / 256), 256>>>(features, fh, fl, n4);
    wprod_kernel<<<dim3(HD / 16, HD / 16), 256>>>(Wk, Wq, t1h, t1l);
    cvec_kernel<<<HD / 64, 256>>>(bq, Wk, cv);

    // 2) qw = f @ W1 + c  (3-pass, split fp16 out)
    mma_gemm<0,3,2><<<dim3(HD / 128, NR / 128), 128, SM3>>>(
        fh, fl, t1h, t1l, cv, nullptr, qh, ql, NR, HD, HD);

    // 3) split memory; memT
    split_kernel<<<(unsigned)((n4 + 255) / 256), 256>>>(memoryf, mh, ml, n4);
    transpose_h<<<dim3(MR / 32, HD / 32), 256>>>(memoryf, mth);

    // 4) S = qw @ mem^T  (3-pass, fp32 out)
    mma_gemm<1,3,2><<<dim3(MR / 128, NR / 128), 128, SM3>>>(
        qh, ql, mh, ml, nullptr, s, nullptr, nullptr, NR, MR, HD);

    // 5) softmax -> fp16 P (hi only)
    softmax_h<<<NR, 512>>>(s, ph, MR);

    // 6) out = 0.5*features + 0.5*(P @ memT^T)  (1-pass fp16, 4-stage)
    mma_gemm<2,1,4><<<dim3(HD / 128, NR / 128), 128, SM1>>>(
        ph, nullptr, mth, nullptr, features, out, nullptr, nullptr, NR, HD, MR);
}

// round 10
// speedup vs baseline: 4.2553x; 1.0014x over previous
#include <cuda_runtime.h>
#include <cuda_fp16.h>
#include <cstdint>
#include <cstddef>

#define NR 8192
#define MR 8192
#define HD 512

// ---------------- scratch (device globals: allowed) ----------------
__device__ __align__(128) __half g_fh[(size_t)NR * HD], g_fl[(size_t)NR * HD];
__device__ __align__(128) __half g_mh[(size_t)MR * HD], g_ml[(size_t)MR * HD];
__device__ __align__(128) __half g_t1h[HD * HD], g_t1l[HD * HD];
__device__ __align__(128) float  g_c[HD];
__device__ __align__(128) __half g_qh[(size_t)NR * HD], g_ql[(size_t)NR * HD];
__device__ __align__(128) __half g_mth[(size_t)HD * MR];
__device__ __align__(128) float  g_s[(size_t)NR * MR];
__device__ __align__(128) __half g_ph[(size_t)NR * MR];

// ---------------- helpers ----------------
__device__ __forceinline__ uint32_t smem_u32(const void* p) {
    uint32_t a;
    asm("{ .reg .u64 t; cvta.to.shared.u64 t, %1; cvt.u32.u64 %0, t; }" : "=r"(a) : "l"(p));
    return a;
}
__device__ __forceinline__ void cp16(uint32_t dst, const void* src) {
    asm volatile("cp.async.cg.shared.global [%0], [%1], 16;" :: "r"(dst), "l"(src));
}
__device__ __forceinline__ void ldsm4(uint32_t* r, uint32_t addr) {
    asm volatile("ldmatrix.sync.aligned.m8n8.x4.shared.b16 {%0,%1,%2,%3}, [%4];"
        : "=r"(r[0]), "=r"(r[1]), "=r"(r[2]), "=r"(r[3]) : "r"(addr));
}
__device__ __forceinline__ void mma16816(float* c, const uint32_t* a, const uint32_t* b) {
    asm volatile("mma.sync.aligned.m16n8k16.row.col.f32.f16.f16.f32 "
        "{%0,%1,%2,%3}, {%4,%5,%6,%7}, {%8,%9}, {%0,%1,%2,%3};"
        : "+f"(c[0]), "+f"(c[1]), "+f"(c[2]), "+f"(c[3])
        : "r"(a[0]), "r"(a[1]), "r"(a[2]), "r"(a[3]), "r"(b[0]), "r"(b[1]));
}
__device__ __forceinline__ void split1(float v, __half& h, __half& l) {
    h = __float2half_rn(v);
    l = __float2half_rn(v - __half2float(h));
}
__device__ __forceinline__ uint32_t pack2(__half a, __half b) {
    __half2 t = __halves2half2(a, b);
    return *(uint32_t*)&t;
}

// pitch: 32 halfs of data padded to 40 halfs (80B) -> conflict-free ldmatrix
#define PITCH_B 80
#define MAT_B   (128 * PITCH_B)   // 10240 B per matrix tile

// ---------------- elementwise fp32 -> (hi, lo) fp16 ----------------
__global__ __launch_bounds__(256)
void split_kernel(const float* __restrict__ s, __half* __restrict__ dh,
                  __half* __restrict__ dl, size_t n4)
{
    size_t i = (size_t)blockIdx.x * blockDim.x + threadIdx.x;
    if (i >= n4) return;
    float4 v = ((const float4*)s)[i];
    __half hx, lx, hy, ly, hz, lz, hw, lw;
    split1(v.x, hx, lx); split1(v.y, hy, ly);
    split1(v.z, hz, lz); split1(v.w, hw, lw);
    ((uint2*)dh)[i] = make_uint2(pack2(hx, hy), pack2(hz, hw));
    ((uint2*)dl)[i] = make_uint2(pack2(lx, ly), pack2(lz, lw));
}

// ---------------- T1 = Wk^T @ Wq (fp32), split-fp16 output ----------------
__global__ __launch_bounds__(256)
void wprod_kernel(const float* __restrict__ Wk, const float* __restrict__ Wq,
                  __half* __restrict__ Th, __half* __restrict__ Tl)
{
    __shared__ float Ks[16][17], Qs[16][17];
    const int i0 = blockIdx.x * 16;
    const int j0 = blockIdx.y * 16;
    const int tx = threadIdx.x & 15;
    const int ty = threadIdx.x >> 4;
    float acc = 0.f;
    for (int t0 = 0; t0 < HD; t0 += 16) {
        Ks[ty][tx] = Wk[(t0 + ty) * HD + i0 + tx];
        Qs[ty][tx] = Wq[(t0 + ty) * HD + j0 + tx];
        __syncthreads();
#pragma unroll
        for (int t = 0; t < 16; ++t)
            acc = fmaf(Ks[t][ty], Qs[t][tx], acc);
        __syncthreads();
    }
    __half h, l; split1(acc, h, l);
    Th[(size_t)(i0 + ty) * HD + j0 + tx] = h;
    Tl[(size_t)(i0 + ty) * HD + j0 + tx] = l;
}

// ---------------- c = bq @ Wk, parallel ----------------
__global__ __launch_bounds__(256)
void cvec_kernel(const float* __restrict__ bq, const float* __restrict__ Wk,
                 float* __restrict__ c)
{
    __shared__ float sm[4][64];
    const int tid = threadIdx.x;
    const int j = blockIdx.x * 64 + (tid & 63);
    const int ts = (tid >> 6) * 128;
    float a = 0.f;
#pragma unroll 4
    for (int t = ts; t < ts + 128; ++t) a = fmaf(bq[t], Wk[t * HD + j], a);
    sm[tid >> 6][tid & 63] = a;
    __syncthreads();
    if (tid < 64)
        c[blockIdx.x * 64 + tid] = (sm[0][tid] + sm[1][tid]) + (sm[2][tid] + sm[3][tid]);
}

// ---------------- mem [MR][HD] fp32 -> memT [HD][MR] fp16 (hi only) ----------------
__global__ __launch_bounds__(256)
void transpose_h(const float* __restrict__ src, __half* __restrict__ dh)
{
    __shared__ float t[32][33];
    const int j0 = blockIdx.x * 32;
    const int h0 = blockIdx.y * 32;
    const int tx = threadIdx.x & 31;
    const int ty = threadIdx.x >> 5;
#pragma unroll
    for (int i = 0; i < 4; ++i)
        t[ty + i * 8][tx] = src[(size_t)(j0 + ty + i * 8) * HD + h0 + tx];
    __syncthreads();
#pragma unroll
    for (int i = 0; i < 4; ++i) {
        size_t o = (size_t)(h0 + ty + i * 8) * MR + j0 + tx;
        dh[o] = __float2half_rn(t[tx][ty + i * 8]);
    }
}

// ---------------------------------------------------------------------------
// NT GEMM via mma.sync, fp32 accumulate. FAT-WARP layout:
// CTA 128x128, 128 threads, 4 warps 2x2, warp tile 64x64 (128 accum regs/thr).
// NPASS==3: D = Ah*Bh + Ah*Bl + Al*Bh   (stage mats: Ah,Bh,Bl,Al)
// NPASS==1: D = Ah*Bh                   (stage mats: Ah,Bh)
// Inner loop is PASS-MAJOR: same accumulator is re-consumed only every
// 16 MMAs (~64 cyc), above HMMA fp32-acc latency -> no dependency stalls.
// K-chunk 32, NSTG-stage cp.async pipeline, single barrier per chunk, 2 CTAs/SM.
// EPI: 0 = +bias[n], split fp16 out; 1 = fp32 out; 2 = 0.5*F + 0.5*acc (F=biasF)
// ---------------------------------------------------------------------------
template <int EPI, int NPASS, int NSTG>
__global__ __launch_bounds__(128, 2)
void mma_gemm(const __half* __restrict__ Ah, const __half* __restrict__ Al,
              const __half* __restrict__ Bh, const __half* __restrict__ Bl,
              const float* __restrict__ biasF,
              float* __restrict__ outf,
              __half* __restrict__ outh, __half* __restrict__ outl,
              int M, int N, int K)
{
    constexpr int NMAT = (NPASS == 3) ? 4 : 2;
    constexpr uint32_t STAGE = NMAT * MAT_B;

    extern __shared__ char smem[];
    const uint32_t sbase = smem_u32(smem);
    const int tid = threadIdx.x;
    const int wid = tid >> 5;           // 0..3
    const int lane = tid & 31;
    const int bm = blockIdx.y * 128;
    const int bn = blockIdx.x * 128;
    const int wm = (wid & 1) * 64;
    const int wn = (wid >> 1) * 64;

    const int NC = K >> 5;

    const int ldr = tid >> 2;           // 0..31
    const int ldc = (tid & 3) * 16;

    auto loadc = [&](int c) {
        const uint32_t sb = sbase + (uint32_t)(c % NSTG) * STAGE;
        const int k0 = c << 5;
        const __half* pa = Ah + (size_t)(bm + ldr) * K + k0 + ldc / 2;
        const __half* pb = Bh + (size_t)(bn + ldr) * K + k0 + ldc / 2;
#pragma unroll
        for (int i = 0; i < 4; ++i) {
            cp16(sb + (ldr + i * 32) * PITCH_B + ldc,         pa + (size_t)(i * 32) * K);
            cp16(sb + MAT_B + (ldr + i * 32) * PITCH_B + ldc, pb + (size_t)(i * 32) * K);
        }
        if (NPASS == 3) {
            const __half* pc = Bl + (size_t)(bn + ldr) * K + k0 + ldc / 2;
            const __half* pd = Al + (size_t)(bm + ldr) * K + k0 + ldc / 2;
#pragma unroll
            for (int i = 0; i < 4; ++i) {
                cp16(sb + 2 * MAT_B + (ldr + i * 32) * PITCH_B + ldc, pc + (size_t)(i * 32) * K);
                cp16(sb + 3 * MAT_B + (ldr + i * 32) * PITCH_B + ldc, pd + (size_t)(i * 32) * K);
            }
        }
    };

    float acc[4][8][4];
#pragma unroll
    for (int mg = 0; mg < 4; ++mg)
#pragma unroll
        for (int ng = 0; ng < 8; ++ng)
#pragma unroll
            for (int j = 0; j < 4; ++j) acc[mg][ng][j] = 0.f;

    const uint32_t aRow = (lane & 15);
    const uint32_t aChk = (lane >> 4);
    const uint32_t bRow = ((lane >> 4) & 1) * 8 + (lane & 7);
    const uint32_t bChk = (lane >> 3) & 1;

    auto compute = [&](int c) {
        const uint32_t st = sbase + (uint32_t)(c % NSTG) * STAGE;
#pragma unroll
        for (int ks = 0; ks < 2; ++ks) {
            // load ALL A fragments for this k16 step
            uint32_t ah[4][4], al[4][4];
#pragma unroll
            for (int mg = 0; mg < 4; ++mg) {
                uint32_t off = (wm + mg * 16 + aRow) * PITCH_B + aChk * 16 + ks * 32;
                ldsm4(ah[mg], st + off);
                if (NPASS == 3) ldsm4(al[mg], st + 3 * MAT_B + off);
            }
            // p-pair granularity: load b frags for two n-groups, then issue
            // pass-major MMA bursts (16 independent MMAs per pass).
#pragma unroll
            for (int ph = 0; ph < 2; ++ph) {
                uint32_t bh[2][4], bl[2][4];
#pragma unroll
                for (int p2 = 0; p2 < 2; ++p2) {
                    uint32_t off = (wn + (ph * 2 + p2) * 16 + bRow) * PITCH_B + bChk * 16 + ks * 32;
                    ldsm4(bh[p2], st + MAT_B + off);
                    if (NPASS == 3) ldsm4(bl[p2], st + 2 * MAT_B + off);
                }
                // pass 1: Ah * Bh
#pragma unroll
                for (int p2 = 0; p2 < 2; ++p2)
#pragma unroll
                    for (int mg = 0; mg < 4; ++mg) {
                        const int ng = 2 * (ph * 2 + p2);
                        mma16816(acc[mg][ng + 0], ah[mg], bh[p2] + 0);
                        mma16816(acc[mg][ng + 1], ah[mg], bh[p2] + 2);
                    }
                if (NPASS == 3) {
                    // pass 2: Ah * Bl
#pragma unroll
                    for (int p2 = 0; p2 < 2; ++p2)
#pragma unroll
                        for (int mg = 0; mg < 4; ++mg) {
                            const int ng = 2 * (ph * 2 + p2);
                            mma16816(acc[mg][ng + 0], ah[mg], bl[p2] + 0);
                            mma16816(acc[mg][ng + 1], ah[mg], bl[p2] + 2);
                        }
                    // pass 3: Al * Bh
#pragma unroll
                    for (int p2 = 0; p2 < 2; ++p2)
#pragma unroll
                        for (int mg = 0; mg < 4; ++mg) {
                            const int ng = 2 * (ph * 2 + p2);
                            mma16816(acc[mg][ng + 0], al[mg], bh[p2] + 0);
                            mma16816(acc[mg][ng + 1], al[mg], bh[p2] + 2);
                        }
                }
            }
        }
    };

    // pipeline: wait(chunk c) -> sync -> prefetch(c+NSTG-1) -> compute(c)
#pragma unroll 1
    for (int c = 0; c < NSTG - 1 && c < NC; ++c) {
        loadc(c);
        asm volatile("cp.async.commit_group;" ::: "memory");
    }
#pragma unroll 1
    for (int c = 0; c < NC; ++c) {
        if (NSTG >= 4 && c + 2 < NC)
            asm volatile("cp.async.wait_group 2;" ::: "memory");
        else if (NSTG >= 3 && c + 1 < NC)
            asm volatile("cp.async.wait_group 1;" ::: "memory");
        else
            asm volatile("cp.async.wait_group 0;" ::: "memory");
        __syncthreads();
        if (c + NSTG - 1 < NC) {
            loadc(c + NSTG - 1);
            asm volatile("cp.async.commit_group;" ::: "memory");
        }
        compute(c);
    }

    // ---------------- epilogue ----------------
#pragma unroll
    for (int mg = 0; mg < 4; ++mg) {
        const int r0 = bm + wm + mg * 16 + (lane >> 2);
#pragma unroll
        for (int ng = 0; ng < 8; ++ng) {
            const int cc = bn + wn + ng * 8 + (lane & 3) * 2;
            const float* a = acc[mg][ng];
            if (EPI == 0) {
                float b0 = biasF[cc], b1 = biasF[cc + 1];
                float v0 = a[0] + b0, v1 = a[1] + b1;
                float v2 = a[2] + b0, v3 = a[3] + b1;
                __half h0, l0, h1, l1, h2, l2, h3, l3;
                split1(v0, h0, l0); split1(v1, h1, l1);
                split1(v2, h2, l2); split1(v3, h3, l3);
                *(uint32_t*)(outh + (size_t)r0 * N + cc)       = pack2(h0, h1);
                *(uint32_t*)(outl + (size_t)r0 * N + cc)       = pack2(l0, l1);
                *(uint32_t*)(outh + (size_t)(r0 + 8) * N + cc) = pack2(h2, h3);
                *(uint32_t*)(outl + (size_t)(r0 + 8) * N + cc) = pack2(l2, l3);
            } else if (EPI == 1) {
                *(float2*)(outf + (size_t)r0 * N + cc)       = make_float2(a[0], a[1]);
                *(float2*)(outf + (size_t)(r0 + 8) * N + cc) = make_float2(a[2], a[3]);
            } else {
                size_t o0 = (size_t)r0 * N + cc, o1 = (size_t)(r0 + 8) * N + cc;
                float2 f0 = *(const float2*)(biasF + o0);
                float2 f1 = *(const float2*)(biasF + o1);
                *(float2*)(outf + o0) = make_float2(0.5f * f0.x + 0.5f * a[0],
                                                    0.5f * f0.y + 0.5f * a[1]);
                *(float2*)(outf + o1) = make_float2(0.5f * f1.x + 0.5f * a[2],
                                                    0.5f * f1.y + 0.5f * a[3]);
            }
        }
    }
}

// ---------------- rowwise softmax: fp32 in, fp16 (hi only) out ----------------
__global__ __launch_bounds__(512)
void softmax_h(const float* __restrict__ S, __half* __restrict__ Ph, int cols)
{
    __shared__ float red[16];
    const int tid = threadIdx.x;
    const float4* p = (const float4*)(S + (size_t)blockIdx.x * cols);
    uint2* oh = (uint2*)(Ph + (size_t)blockIdx.x * cols);

    float4 v[4];
    float m = -1e30f;
#pragma unroll
    for (int i = 0; i < 4; ++i) {
        v[i] = p[tid + i * 512];
        m = fmaxf(m, fmaxf(fmaxf(v[i].x, v[i].y), fmaxf(v[i].z, v[i].w)));
    }
#pragma unroll
    for (int o = 16; o; o >>= 1) m = fmaxf(m, __shfl_xor_sync(0xffffffffu, m, o));
    if ((tid & 31) == 0) red[tid >> 5] = m;
    __syncthreads();
    if (tid < 32) {
        float t = (tid < 16) ? red[tid] : -1e30f;
#pragma unroll
        for (int o = 8; o; o >>= 1) t = fmaxf(t, __shfl_xor_sync(0xffffffffu, t, o));
        if (tid == 0) red[0] = t;
    }
    __syncthreads();
    m = red[0];
    __syncthreads();

    float sum = 0.f;
#pragma unroll
    for (int i = 0; i < 4; ++i) {
        v[i].x = __expf(v[i].x - m); v[i].y = __expf(v[i].y - m);
        v[i].z = __expf(v[i].z - m); v[i].w = __expf(v[i].w - m);
        sum += (v[i].x + v[i].y) + (v[i].z + v[i].w);
    }
#pragma unroll
    for (int o = 16; o; o >>= 1) sum += __shfl_xor_sync(0xffffffffu, sum, o);
    if ((tid & 31) == 0) red[tid >> 5] = sum;
    __syncthreads();
    if (tid < 32) {
        float t = (tid < 16) ? red[tid] : 0.f;
#pragma unroll
        for (int o = 8; o; o >>= 1) t += __shfl_xor_sync(0xffffffffu, t, o);
        if (tid == 0) red[0] = t;
    }
    __syncthreads();
    const float inv = 1.0f / red[0];

#pragma unroll
    for (int i = 0; i < 4; ++i) {
        oh[tid + i * 512] = make_uint2(
            pack2(__float2half_rn(v[i].x * inv), __float2half_rn(v[i].y * inv)),
            pack2(__float2half_rn(v[i].z * inv), __float2half_rn(v[i].w * inv)));
    }
}

// ---------------------------------------------------------------------------
extern "C" void kernel_launch(void* const* d_in, const int* in_sizes, int n_in,
                              void* d_out, int out_size)
{
    const float* features = (const float*)d_in[0];
    const float* memoryf  = (const float*)d_in[1];
    const float* Wq       = (const float*)d_in[2];
    const float* bq       = (const float*)d_in[3];
    const float* Wk       = (const float*)d_in[4];
    // bk cancels in softmax (per-row logit constant) -> unused
    float* out            = (float*)d_out;

    __half *fh, *fl, *mh, *ml, *t1h, *t1l, *qh, *ql, *mth, *ph;
    float *s, *cv;
    cudaGetSymbolAddress((void**)&fh, g_fh);   cudaGetSymbolAddress((void**)&fl, g_fl);
    cudaGetSymbolAddress((void**)&mh, g_mh);   cudaGetSymbolAddress((void**)&ml, g_ml);
    cudaGetSymbolAddress((void**)&t1h, g_t1h); cudaGetSymbolAddress((void**)&t1l, g_t1l);
    cudaGetSymbolAddress((void**)&qh, g_qh);   cudaGetSymbolAddress((void**)&ql, g_ql);
    cudaGetSymbolAddress((void**)&mth, g_mth); cudaGetSymbolAddress((void**)&ph, g_ph);
    cudaGetSymbolAddress((void**)&s, g_s);     cudaGetSymbolAddress((void**)&cv, g_c);

    const int SM3 = 2 * 4 * MAT_B;   // 81920 B : 3-pass, 2 stages
    const int SM1 = 4 * 2 * MAT_B;   // 81920 B : 1-pass, 4 stages
    cudaFuncSetAttribute(mma_gemm<0,3,2>, cudaFuncAttributeMaxDynamicSharedMemorySize, SM3);
    cudaFuncSetAttribute(mma_gemm<1,3,2>, cudaFuncAttributeMaxDynamicSharedMemorySize, SM3);
    cudaFuncSetAttribute(mma_gemm<2,1,4>, cudaFuncAttributeMaxDynamicSharedMemorySize, SM1);

    size_t n4 = (size_t)NR * HD / 4;

    // 1) split features; W-product; bias fold
    split_kernel<<<(unsigned)((n4 + 255) / 256), 256>>>(features, fh, fl, n4);
    wprod_kernel<<<dim3(HD / 16, HD / 16), 256>>>(Wk, Wq, t1h, t1l);
    cvec_kernel<<<HD / 64, 256>>>(bq, Wk, cv);

    // 2) qw = f @ W1 + c  (3-pass, split fp16 out)
    mma_gemm<0,3,2><<<dim3(HD / 128, NR / 128), 128, SM3>>>(
        fh, fl, t1h, t1l, cv, nullptr, qh, ql, NR, HD, HD);

    // 3) split memory; memT
    split_kernel<<<(unsigned)((n4 + 255) / 256), 256>>>(memoryf, mh, ml, n4);
    transpose_h<<<dim3(MR / 32, HD / 32), 256>>>(memoryf, mth);

    // 4) S = qw @ mem^T  (3-pass, fp32 out)
    mma_gemm<1,3,2><<<dim3(MR / 128, NR / 128), 128, SM3>>>(
        qh, ql, mh, ml, nullptr, s, nullptr, nullptr, NR, MR, HD);

    // 5) softmax -> fp16 P (hi only)
    softmax_h<<<NR, 512>>>(s, ph, MR);

    // 6) out = 0.5*features + 0.5*(P @ memT^T)  (1-pass fp16, 4-stage)
    mma_gemm<2,1,4><<<dim3(HD / 128, NR / 128), 128, SM1>>>(
        ph, nullptr, mth, nullptr, features, out, nullptr, nullptr, NR, HD, MR);
}